// round 12
// baseline (speedup 1.0000x reference)
#include <cuda_runtime.h>
#include <cuda_bf16.h>
#include <cuda_fp16.h>
#include <cstdint>

// Problem constants
#define BATCH   8
#define SEQ     1024
#define DIM     768
#define HEADS   12
#define HDIM    64
#define INNER   768
#define TRIPLE  2304
#define SCALE   0.125f

typedef __nv_bfloat16 bf16;
typedef __half f16;

// ---------------- static scratch ----------------
__device__ __align__(128) f16 g_e[(size_t)BATCH * HEADS * SEQ * SEQ];   // E = exp(S)/16
__device__ __align__(128) f16 g_rinv[(size_t)BATCH * SEQ * SEQ];        // 1/sum_h E

__device__ __align__(128) f16 g_xh16[BATCH * SEQ * DIM];
__device__ __align__(128) f16 g_xl16[BATCH * SEQ * DIM];
__device__ __align__(128) f16 g_wq16[TRIPLE * DIM];     // transposed, hi only
__device__ __align__(128) f16 g_wo16[DIM * INNER];      // transposed, hi only
__device__ __align__(128) f16 g_oh16[BATCH * SEQ * INNER];
__device__ __align__(128) f16 g_ol16[BATCH * SEQ * INNER];

__device__ __align__(128) f16 g_qh16[BATCH * HEADS * SEQ * HDIM];
__device__ __align__(128) f16 g_ql16[BATCH * HEADS * SEQ * HDIM];
__device__ __align__(128) f16 g_kh16[BATCH * HEADS * SEQ * HDIM];
__device__ __align__(128) f16 g_vh16[BATCH * HEADS * SEQ * HDIM];
__device__ __align__(128) f16 g_vl16[BATCH * HEADS * SEQ * HDIM];

// ================= helpers =================
__device__ __forceinline__ uint32_t smem_to_u32(const void* p) {
    uint32_t a;
    asm("{ .reg .u64 t; cvta.to.shared.u64 t, %1; cvt.u32.u64 %0, t; }"
        : "=r"(a) : "l"(p));
    return a;
}
// swizzled byte offset within a [rows x 32 elems(16b)] tile (64B per row)
__device__ __forceinline__ uint32_t swz(uint32_t r, uint32_t c) {
    return (r * 4 + (c ^ ((r >> 1) & 3))) * 16;
}
__device__ __forceinline__ void ldmatrix_x4(uint32_t& r0, uint32_t& r1,
                                            uint32_t& r2, uint32_t& r3,
                                            uint32_t addr) {
    asm volatile("ldmatrix.sync.aligned.m8n8.x4.shared.b16 {%0,%1,%2,%3}, [%4];"
                 : "=r"(r0), "=r"(r1), "=r"(r2), "=r"(r3) : "r"(addr));
}
__device__ __forceinline__ void ldmatrix_x4_trans(uint32_t& r0, uint32_t& r1,
                                                  uint32_t& r2, uint32_t& r3,
                                                  uint32_t addr) {
    asm volatile("ldmatrix.sync.aligned.m8n8.x4.trans.shared.b16 {%0,%1,%2,%3}, [%4];"
                 : "=r"(r0), "=r"(r1), "=r"(r2), "=r"(r3) : "r"(addr));
}
__device__ __forceinline__ void mma_f16(float* c, const uint32_t* a,
                                        uint32_t b0, uint32_t b1) {
    asm volatile("mma.sync.aligned.m16n8k16.row.col.f32.f16.f16.f32 "
                 "{%0,%1,%2,%3}, {%4,%5,%6,%7}, {%8,%9}, {%0,%1,%2,%3};"
                 : "+f"(c[0]), "+f"(c[1]), "+f"(c[2]), "+f"(c[3])
                 : "r"(a[0]), "r"(a[1]), "r"(a[2]), "r"(a[3]),
                   "r"(b0), "r"(b1));
}
__device__ __forceinline__ uint32_t hmul2u(uint32_t a, uint32_t b) {
    __half2 r = __hmul2(*(__half2*)&a, *(__half2*)&b);
    return *(uint32_t*)&r;
}
#define CP_ASYNC16(sa, g) \
    asm volatile("cp.async.cg.shared.global [%0], [%1], 16;" :: "r"(sa), "l"(g))
#define CP_COMMIT() asm volatile("cp.async.commit_group;" ::: "memory")
#define CP_WAIT2()  asm volatile("cp.async.wait_group 2;" ::: "memory")
#define CP_WAIT1()  asm volatile("cp.async.wait_group 1;" ::: "memory")
#define CP_WAIT0()  asm volatile("cp.async.wait_group 0;" ::: "memory")

__device__ __forceinline__ float fast_exp_s(float x) {
    const float LOG2E = 1.4426950408889634f;
    const float MAGIC = 12582912.0f;
    float z = fmaf(x, LOG2E, MAGIC);
    int   e = __float_as_int(z) - 0x4B400000;
    float i = z - MAGIC;
    float f = fmaf(x, LOG2E, -i);
    float p = 1.5403531e-4f;
    p = fmaf(p, f, 1.3333558e-3f);
    p = fmaf(p, f, 9.6181291e-3f);
    p = fmaf(p, f, 5.5504109e-2f);
    p = fmaf(p, f, 2.4022651e-1f);
    p = fmaf(p, f, 6.9314718e-1f);
    p = fmaf(p, f, 1.0f);
    return __int_as_float(__float_as_int(p) + ((e - 4) << 23));
}
__device__ __forceinline__ void split2h(float2 v, __half2& h, __half2& l) {
    f16 hx = __float2half_rn(v.x), hy = __float2half_rn(v.y);
    h = __half2(hx, hy);
    l = __half2(__float2half_rn(v.x - __half2float(hx)),
                __float2half_rn(v.y - __half2float(hy)));
}

// =========================================================================
// Prep kernels
// =========================================================================
__global__ __launch_bounds__(256) void split_f16_kernel(
    const float* __restrict__ in, f16* __restrict__ hi, f16* __restrict__ lo, int n4)
{
    int i = blockIdx.x * 256 + threadIdx.x;
    if (i >= n4) return;
    float4 v = ((const float4*)in)[i];
    __half2 h0, l0, h1, l1;
    split2h(make_float2(v.x, v.y), h0, l0);
    split2h(make_float2(v.z, v.w), h1, l1);
    __half2* H = (__half2*)hi;
    __half2* L = (__half2*)lo;
    H[2 * i] = h0; H[2 * i + 1] = h1;
    L[2 * i] = l0; L[2 * i + 1] = l1;
}

__global__ __launch_bounds__(256) void transpose_f16_kernel(
    const float* __restrict__ in, f16* __restrict__ outp, int R, int C)
{
    __shared__ float t[32][33];
    const int tx = threadIdx.x, ty = threadIdx.y;
    const int bx = blockIdx.x, by = blockIdx.y;
    #pragma unroll
    for (int i = 0; i < 4; i++) {
        int r = by * 32 + ty + i * 8;
        t[ty + i * 8][tx] = in[(size_t)r * C + bx * 32 + tx];
    }
    __syncthreads();
    #pragma unroll
    for (int i = 0; i < 4; i++) {
        int c = bx * 32 + ty + i * 8;
        int r = by * 32 + tx;
        outp[(size_t)c * R + r] = __float2half_rn(t[tx][ty + i * 8]);
    }
}

// =========================================================================
// fp16 2-MMA GEMM: C = (Ah+Al) @ Bw^T. 128x128x32, 4-stage, 1 barrier/iter.
// =========================================================================
#define MAT_BYTES  8192
#define STG_BYTES  (3 * MAT_BYTES)
#define HM_STAGES  4
#define HM_SMEM_BYTES (HM_STAGES * STG_BYTES)   // 98304

__global__ __launch_bounds__(256, 2) void hmma_f16_gemm_kernel(
    const f16* __restrict__ Ah, const f16* __restrict__ Al,
    const f16* __restrict__ Bw,
    const float* __restrict__ bias, float* __restrict__ outp, int mode)
{
    extern __shared__ f16 sm[];
    const int tid = threadIdx.x, lane = tid & 31, wid = tid >> 5;
    const int wr = wid >> 1, wc = wid & 1;
    const int bn = blockIdx.x * 128, bm = blockIdx.y * 128;
    const uint32_t smem_base = smem_to_u32(sm);

    const f16* srcs[3] = {Ah, Al, Bw};
    const int rb[3] = {bm, bm, bn};

    float acc[2][8][4] = {};

    const int lr0 = tid >> 2, lr1 = (tid + 256) >> 2;
    const int lc = tid & 3;

    auto issue = [&](int it, int s) {
        const int k0 = it * 32;
        const uint32_t sb = smem_base + (uint32_t)(s * STG_BYTES);
        #pragma unroll
        for (int m = 0; m < 3; m++) {
            const f16* src = srcs[m];
            CP_ASYNC16(sb + m * MAT_BYTES + swz(lr0, lc),
                       src + (size_t)(rb[m] + lr0) * DIM + k0 + lc * 8);
            CP_ASYNC16(sb + m * MAT_BYTES + swz(lr1, lc),
                       src + (size_t)(rb[m] + lr1) * DIM + k0 + lc * 8);
        }
        CP_COMMIT();
    };

    const int NIT = DIM / 32;   // 24
    issue(0, 0);
    issue(1, 1);
    issue(2, 2);

    for (int it = 0; it < NIT; ++it) {
        if (it + 2 < NIT)      { CP_WAIT2(); }
        else if (it + 1 < NIT) { CP_WAIT1(); }
        else                   { CP_WAIT0(); }
        __syncthreads();
        if (it + 3 < NIT) issue(it + 3, (it + 3) % HM_STAGES);

        const uint32_t sb = smem_base + (uint32_t)((it % HM_STAGES) * STG_BYTES);
        #pragma unroll
        for (int ks = 0; ks < 2; ks++) {
            const uint32_t c0 = ks * 2 + (lane >> 4);
            uint32_t ah[2][4], al[2][4], bf[4][4];
            #pragma unroll
            for (int mt = 0; mt < 2; mt++) {
                uint32_t r = wr * 32 + mt * 16 + (lane & 15);
                ldmatrix_x4(ah[mt][0], ah[mt][1], ah[mt][2], ah[mt][3],
                            sb + 0 * MAT_BYTES + swz(r, c0));
                ldmatrix_x4(al[mt][0], al[mt][1], al[mt][2], al[mt][3],
                            sb + 1 * MAT_BYTES + swz(r, c0));
            }
            #pragma unroll
            for (int p = 0; p < 4; p++) {
                uint32_t r = wc * 64 + p * 16 + (lane & 15);
                ldmatrix_x4(bf[p][0], bf[p][1], bf[p][2], bf[p][3],
                            sb + 2 * MAT_BYTES + swz(r, c0));
            }
            #pragma unroll
            for (int p = 0; p < 4; p++)
                #pragma unroll
                for (int mt = 0; mt < 2; mt++) {
                    mma_f16(acc[mt][2 * p + 0], ah[mt], bf[p][0], bf[p][2]);
                    mma_f16(acc[mt][2 * p + 1], ah[mt], bf[p][1], bf[p][3]);
                }
            #pragma unroll
            for (int p = 0; p < 4; p++)
                #pragma unroll
                for (int mt = 0; mt < 2; mt++) {
                    mma_f16(acc[mt][2 * p + 0], al[mt], bf[p][0], bf[p][2]);
                    mma_f16(acc[mt][2 * p + 1], al[mt], bf[p][1], bf[p][3]);
                }
        }
    }

    // ---- epilogue ----
    #pragma unroll
    for (int mt = 0; mt < 2; mt++) {
        const int r = bm + wr * 32 + mt * 16 + (lane >> 2);
        #pragma unroll
        for (int nt = 0; nt < 8; nt++) {
            const int c = bn + wc * 64 + nt * 8 + 2 * (lane & 3);
            float2 v0 = make_float2(acc[mt][nt][0], acc[mt][nt][1]);
            float2 v1 = make_float2(acc[mt][nt][2], acc[mt][nt][3]);
            if (mode == 0) {
                int chunk = c / INNER;
                int e = c % INNER;
                int h = e >> 6, d = e & 63;
                int b0 = r >> 10, n0 = r & 1023;
                int r2 = r + 8;
                int b1 = r2 >> 10, n1 = r2 & 1023;
                size_t i0 = (((size_t)(b0 * HEADS + h) * SEQ) + n0) * HDIM + d;
                size_t i1 = (((size_t)(b1 * HEADS + h) * SEQ) + n1) * HDIM + d;
                if (chunk == 2) {
                    __half2 hh, ll;
                    split2h(v0, hh, ll);
                    *(__half2*)&g_vh16[i0] = hh;
                    *(__half2*)&g_vl16[i0] = ll;
                    split2h(v1, hh, ll);
                    *(__half2*)&g_vh16[i1] = hh;
                    *(__half2*)&g_vl16[i1] = ll;
                } else if (chunk == 0) {
                    v0.x *= SCALE; v0.y *= SCALE;
                    v1.x *= SCALE; v1.y *= SCALE;
                    __half2 hh, ll;
                    split2h(v0, hh, ll);
                    *(__half2*)&g_qh16[i0] = hh;
                    *(__half2*)&g_ql16[i0] = ll;
                    split2h(v1, hh, ll);
                    *(__half2*)&g_qh16[i1] = hh;
                    *(__half2*)&g_ql16[i1] = ll;
                } else {
                    *(__half2*)&g_kh16[i0] = __floats2half2_rn(v0.x, v0.y);
                    *(__half2*)&g_kh16[i1] = __floats2half2_rn(v1.x, v1.y);
                }
            } else {
                float2 bq = *(const float2*)&bias[c];
                v0.x += bq.x; v0.y += bq.y;
                v1.x += bq.x; v1.y += bq.y;
                *(float2*)&outp[(size_t)r * DIM + c] = v0;
                *(float2*)&outp[(size_t)(r + 8) * DIM + c] = v1;
            }
        }
    }
}

// =========================================================================
// Score HMMA v2 (persistent n-tile): one CTA per (bh, n0).
// Q hi/lo resident in smem (loaded once); K tiles streamed 3-stage over
// the 8 m-tiles. E = exp((Qh+Ql).Kh)/16 -> fp16, written per m-iter.
// =========================================================================
#define SGS 72
#define SC_MAT_BYTES (128 * SGS * 2)                 // 18432
#define SC_Q_BYTES   (2 * SC_MAT_BYTES)              // 36864
#define SC_K_STAGES  3
#define SC_SMEM_BYTES (SC_Q_BYTES + SC_K_STAGES * SC_MAT_BYTES)  // 92160

__global__ __launch_bounds__(256, 2) void score_hmma_kernel()
{
    extern __shared__ f16 smh[];
    const int tid = threadIdx.x, lane = tid & 31, wid = tid >> 5;
    const int wr = wid >> 1, wc = wid & 1;
    const int n0 = blockIdx.x * 128;
    const int bh = blockIdx.y;
    const uint32_t smem_base = smem_to_u32(smh);

    const f16* qh = g_qh16 + ((size_t)bh * SEQ + n0) * HDIM;
    const f16* ql = g_ql16 + ((size_t)bh * SEQ + n0) * HDIM;
    const f16* kh = g_kh16 + (size_t)bh * SEQ * HDIM;

    // load coords: 128 rows x 8 chunks = 1024 chunks, 4 per thread
    const int qrow = tid >> 1;                   // 2 chunk-pairs per row? no:
    // use: per thread 4 chunks at rows tid>>1 ... simpler: chunk id loop
    const uint32_t kstg_base = smem_base + SC_Q_BYTES;

    // ---- issue Q (group 0) ----
    {
        #pragma unroll
        for (int m = 0; m < 2; m++) {
            const f16* src = (m == 0) ? qh : ql;
            const uint32_t dst = smem_base + (uint32_t)(m * SC_MAT_BYTES);
            #pragma unroll
            for (int t = 0; t < 4; t++) {
                int i = tid + t * 256;
                int row = i >> 3, ch = i & 7;
                CP_ASYNC16(dst + (uint32_t)(row * SGS + ch * 8) * 2,
                           src + (size_t)row * HDIM + ch * 8);
            }
        }
        CP_COMMIT();
    }
    // ---- K tile issue ----
    auto issueK = [&](int it, int s) {
        const int m0 = it * 128;
        const uint32_t dst = kstg_base + (uint32_t)(s * SC_MAT_BYTES);
        #pragma unroll
        for (int t = 0; t < 4; t++) {
            int i = tid + t * 256;
            int row = i >> 3, ch = i & 7;
            CP_ASYNC16(dst + (uint32_t)(row * SGS + ch * 8) * 2,
                       kh + (size_t)(m0 + row) * HDIM + ch * 8);
        }
        CP_COMMIT();
    };

    const int NIT = SEQ / 128;   // 8
    issueK(0, 0);
    issueK(1, 1);

    f16* ebase = g_e + (size_t)bh * SEQ * SEQ;

    for (int it = 0; it < NIT; ++it) {
        if (it + 1 < NIT) { CP_WAIT1(); } else { CP_WAIT0(); }
        __syncthreads();
        if (it + 2 < NIT) issueK(it + 2, (it + 2) % SC_K_STAGES);

        const uint32_t kb = kstg_base + (uint32_t)((it % SC_K_STAGES) * SC_MAT_BYTES);
        float acc[2][8][4] = {};

        #pragma unroll
        for (int ks = 0; ks < 4; ks++) {
            const uint32_t col = ks * 16 + (lane >> 4) * 8;
            uint32_t ah[2][4], al[2][4], bf[4][4];
            #pragma unroll
            for (int mt = 0; mt < 2; mt++) {
                uint32_t r = wr * 32 + mt * 16 + (lane & 15);
                ldmatrix_x4(ah[mt][0], ah[mt][1], ah[mt][2], ah[mt][3],
                            smem_base + 0 * SC_MAT_BYTES + (r * SGS + col) * 2);
                ldmatrix_x4(al[mt][0], al[mt][1], al[mt][2], al[mt][3],
                            smem_base + 1 * SC_MAT_BYTES + (r * SGS + col) * 2);
            }
            #pragma unroll
            for (int p = 0; p < 4; p++) {
                uint32_t r = wc * 64 + p * 16 + (lane & 15);
                ldmatrix_x4(bf[p][0], bf[p][1], bf[p][2], bf[p][3],
                            kb + (r * SGS + col) * 2);
            }
            #pragma unroll
            for (int p = 0; p < 4; p++)
                #pragma unroll
                for (int mt = 0; mt < 2; mt++) {
                    mma_f16(acc[mt][2 * p + 0], ah[mt], bf[p][0], bf[p][2]);
                    mma_f16(acc[mt][2 * p + 1], ah[mt], bf[p][1], bf[p][3]);
                }
            #pragma unroll
            for (int p = 0; p < 4; p++)
                #pragma unroll
                for (int mt = 0; mt < 2; mt++) {
                    mma_f16(acc[mt][2 * p + 0], al[mt], bf[p][0], bf[p][2]);
                    mma_f16(acc[mt][2 * p + 1], al[mt], bf[p][1], bf[p][3]);
                }
        }

        // epilogue for this m-tile
        const int m0 = it * 128;
        #pragma unroll
        for (int mt = 0; mt < 2; mt++) {
            const int r = n0 + wr * 32 + mt * 16 + (lane >> 2);
            #pragma unroll
            for (int nt = 0; nt < 8; nt++) {
                const int c = m0 + wc * 64 + nt * 8 + 2 * (lane & 3);
                __half2 e0 = __floats2half2_rn(fast_exp_s(acc[mt][nt][0]),
                                               fast_exp_s(acc[mt][nt][1]));
                __half2 e1 = __floats2half2_rn(fast_exp_s(acc[mt][nt][2]),
                                               fast_exp_s(acc[mt][nt][3]));
                *(__half2*)&ebase[(size_t)r * SEQ + c] = e0;
                *(__half2*)&ebase[(size_t)(r + 8) * SEQ + c] = e1;
            }
        }
    }
}

// =========================================================================
// Sum: rinv[b,n,m] = 1 / sum_h E  (fp16; L2-resident, 16.8 MB)
// =========================================================================
__global__ __launch_bounds__(256) void sum_kernel()
{
    size_t idx = (size_t)blockIdx.x * 256 + threadIdx.x;
    int m4 = idx & 255;
    int n = (idx >> 8) & 1023;
    int b = (int)(idx >> 18);

    const uint2* E = (const uint2*)g_e;
    float4 s = make_float4(0.f, 0.f, 0.f, 0.f);
    #pragma unroll
    for (int h = 0; h < HEADS; h++) {
        size_t off = ((size_t)(b * HEADS + h) * SEQ + n) * (SEQ / 4) + m4;
        uint2 u = E[off];
        float2 f0 = __half22float2(*(__half2*)&u.x);
        float2 f1 = __half22float2(*(__half2*)&u.y);
        s.x += f0.x; s.y += f0.y; s.z += f1.x; s.w += f1.y;
    }
    uint2 o;
    *(__half2*)&o.x = __floats2half2_rn(1.0f / s.x, 1.0f / s.y);
    *(__half2*)&o.y = __floats2half2_rn(1.0f / s.z, 1.0f / s.w);
    ((uint2*)g_rinv)[((size_t)(b * SEQ + n)) * (SEQ / 4) + m4] = o;
}

// =========================================================================
// AV HMMA (fp16): O = (E*rinv) @ V. Unchanged (occ-3 protected).
// =========================================================================
#define AVE_BYTES 8192
#define AVR_BYTES 8192
#define AVV_BYTES 4608
#define AV_STG_BYTES (AVE_BYTES + AVR_BYTES + 2 * AVV_BYTES)  // 25600
#define AV_SMEM_BYTES (3 * AV_STG_BYTES)                      // 76800
#define VGS 72

__global__ __launch_bounds__(256, 3) void av_hmma_kernel()
{
    extern __shared__ f16 smh[];
    const int tid = threadIdx.x, lane = tid & 31, wid = tid >> 5;
    const int wr = wid >> 1, wc = wid & 1;
    const int n0 = blockIdx.x * 128;
    const int bh = blockIdx.y;
    const int b = bh / HEADS, h = bh % HEADS;
    const uint32_t smem_base = smem_to_u32(smh);

    const f16* ep  = g_e    + ((size_t)bh * SEQ + n0) * SEQ;
    const f16* rp  = g_rinv + ((size_t)(b * SEQ + n0)) * SEQ;
    const f16* vhp = g_vh16 + (size_t)bh * SEQ * HDIM;
    const f16* vlp = g_vl16 + (size_t)bh * SEQ * HDIM;

    float acc[2][4][4] = {};

    const int lr0 = tid >> 2, lr1 = (tid + 256) >> 2;
    const int lc = tid & 3;
    const int vrow_ld = tid >> 3, vch_ld = tid & 7;

    auto issue = [&](int it, int s) {
        const int k0 = it * 32;
        const uint32_t sb = smem_base + (uint32_t)(s * AV_STG_BYTES);
        CP_ASYNC16(sb + swz(lr0, lc), ep + (size_t)lr0 * SEQ + k0 + lc * 8);
        CP_ASYNC16(sb + swz(lr1, lc), ep + (size_t)lr1 * SEQ + k0 + lc * 8);
        CP_ASYNC16(sb + AVE_BYTES + swz(lr0, lc), rp + (size_t)lr0 * SEQ + k0 + lc * 8);
        CP_ASYNC16(sb + AVE_BYTES + swz(lr1, lc), rp + (size_t)lr1 * SEQ + k0 + lc * 8);
        uint32_t doff = (uint32_t)(vrow_ld * VGS + vch_ld * 8) * 2;
        CP_ASYNC16(sb + AVE_BYTES + AVR_BYTES + doff,
                   vhp + (size_t)(k0 + vrow_ld) * HDIM + vch_ld * 8);
        CP_ASYNC16(sb + AVE_BYTES + AVR_BYTES + AVV_BYTES + doff,
                   vlp + (size_t)(k0 + vrow_ld) * HDIM + vch_ld * 8);
        CP_COMMIT();
    };

    const int NIT = SEQ / 32;
    issue(0, 0);
    issue(1, 1);

    for (int it = 0; it < NIT; ++it) {
        if (it + 1 < NIT) { CP_WAIT1(); } else { CP_WAIT0(); }
        __syncthreads();
        if (it + 2 < NIT) issue(it + 2, (it + 2) % 3);

        const uint32_t sb = smem_base + (uint32_t)((it % 3) * AV_STG_BYTES);
        const uint32_t rvb = sb + AVE_BYTES;
        const uint32_t vhb = rvb + AVR_BYTES;
        const uint32_t vlb = vhb + AVV_BYTES;

        #pragma unroll
        for (int ks = 0; ks < 2; ks++) {
            const uint32_t c0 = ks * 2 + (lane >> 4);
            uint32_t a[2][4];
            #pragma unroll
            for (int mt = 0; mt < 2; mt++) {
                uint32_t r = wr * 32 + mt * 16 + (lane & 15);
                uint32_t rv[4];
                ldmatrix_x4(a[mt][0], a[mt][1], a[mt][2], a[mt][3],
                            sb + swz(r, c0));
                ldmatrix_x4(rv[0], rv[1], rv[2], rv[3],
                            rvb + swz(r, c0));
                #pragma unroll
                for (int j = 0; j < 4; j++) a[mt][j] = hmul2u(a[mt][j], rv[j]);
            }
            const uint32_t kb = ks * 16;
            #pragma unroll
            for (int nb = 0; nb < 2; nb++) {
                const uint32_t d0 = wc * 32 + nb * 16;
                uint32_t vrow = kb + (lane & 7) + ((lane >> 3) & 1) * 8;
                uint32_t vcol = d0 + (lane >> 4) * 8;
                uint32_t bh0, bh1, bh2, bh3, bl0, bl1, bl2, bl3;
                ldmatrix_x4_trans(bh0, bh1, bh2, bh3, vhb + (vrow * VGS + vcol) * 2);
                ldmatrix_x4_trans(bl0, bl1, bl2, bl3, vlb + (vrow * VGS + vcol) * 2);
                const int nt0 = nb * 2, nt1 = nb * 2 + 1;
                #pragma unroll
                for (int mt = 0; mt < 2; mt++) {
                    mma_f16(acc[mt][nt0], a[mt], bh0, bh1);
                    mma_f16(acc[mt][nt1], a[mt], bh2, bh3);
                }
                #pragma unroll
                for (int mt = 0; mt < 2; mt++) {
                    mma_f16(acc[mt][nt0], a[mt], bl0, bl1);
                    mma_f16(acc[mt][nt1], a[mt], bl2, bl3);
                }
            }
        }
    }

    // epilogue: O -> fp16 hi/lo at [b, n, h*64+d]
    #pragma unroll
    for (int mt = 0; mt < 2; mt++) {
        const int r = n0 + wr * 32 + mt * 16 + (lane >> 2);
        #pragma unroll
        for (int nt = 0; nt < 4; nt++) {
            const int c = wc * 32 + nt * 8 + 2 * (lane & 3);
            float2 v0 = make_float2(acc[mt][nt][0], acc[mt][nt][1]);
            float2 v1 = make_float2(acc[mt][nt][2], acc[mt][nt][3]);
            __half2 hh, ll;
            size_t i0 = ((size_t)(b * SEQ + r)) * INNER + h * HDIM + c;
            split2h(v0, hh, ll);
            *(__half2*)&g_oh16[i0] = hh;
            *(__half2*)&g_ol16[i0] = ll;
            size_t i1 = ((size_t)(b * SEQ + r + 8)) * INNER + h * HDIM + c;
            split2h(v1, hh, ll);
            *(__half2*)&g_oh16[i1] = hh;
            *(__half2*)&g_ol16[i1] = ll;
        }
    }
}

// =========================================================================
extern "C" void kernel_launch(void* const* d_in, const int* in_sizes, int n_in,
                              void* d_out, int out_size)
{
    const float* x     = (const float*)d_in[0];
    const float* w_qkv = (const float*)d_in[1];
    const float* w_out = (const float*)d_in[2];
    const float* b_out = (const float*)d_in[3];
    float* out = (float*)d_out;

    cudaFuncSetAttribute(hmma_f16_gemm_kernel,
                         cudaFuncAttributeMaxDynamicSharedMemorySize, HM_SMEM_BYTES);
    cudaFuncSetAttribute(score_hmma_kernel,
                         cudaFuncAttributeMaxDynamicSharedMemorySize, SC_SMEM_BYTES);
    cudaFuncSetAttribute(av_hmma_kernel,
                         cudaFuncAttributeMaxDynamicSharedMemorySize, AV_SMEM_BYTES);

    f16 *xh, *xl, *wq, *wo, *oh, *ol;
    cudaGetSymbolAddress((void**)&xh, g_xh16);
    cudaGetSymbolAddress((void**)&xl, g_xl16);
    cudaGetSymbolAddress((void**)&wq, g_wq16);
    cudaGetSymbolAddress((void**)&wo, g_wo16);
    cudaGetSymbolAddress((void**)&oh, g_oh16);
    cudaGetSymbolAddress((void**)&ol, g_ol16);

    // Prep
    {
        int n4 = BATCH * SEQ * DIM / 4;
        split_f16_kernel<<<(n4 + 255) / 256, 256>>>(x, xh, xl, n4);
    }
    {
        dim3 grid(TRIPLE / 32, DIM / 32);
        transpose_f16_kernel<<<grid, dim3(32, 8)>>>(w_qkv, wq, DIM, TRIPLE);
    }
    {
        dim3 grid(DIM / 32, INNER / 32);
        transpose_f16_kernel<<<grid, dim3(32, 8)>>>(w_out, wo, INNER, DIM);
    }

    // K1: QKV projection (fp16 2-MMA, 4-stage)
    {
        dim3 grid(TRIPLE / 128, (BATCH * SEQ) / 128);
        hmma_f16_gemm_kernel<<<grid, 256, HM_SMEM_BYTES>>>(xh, xl, wq, nullptr, nullptr, 0);
    }
    // K2: scores -> exp/16 (fp16 E), persistent n-tile
    {
        dim3 grid(SEQ / 128, BATCH * HEADS);   // 8 x 96 = 768
        score_hmma_kernel<<<grid, 256, SC_SMEM_BYTES>>>();
    }
    // K3: rinv = 1/sum_h E
    {
        int total = BATCH * SEQ * (SEQ / 4);
        sum_kernel<<<total / 256, 256>>>();
    }
    // K4: O = (E*rinv) @ V (fp16 HMMA)
    {
        dim3 grid(SEQ / 128, BATCH * HEADS);
        av_hmma_kernel<<<grid, 256, AV_SMEM_BYTES>>>();
    }
    // K5: output projection (fp16 2-MMA, 4-stage) + bias
    {
        dim3 grid(DIM / 128, (BATCH * SEQ) / 128);
        hmma_f16_gemm_kernel<<<grid, 256, HM_SMEM_BYTES>>>(oh, ol, wo, b_out, out, 1);
    }
}

// round 13
// speedup vs baseline: 1.0347x; 1.0347x over previous
#include <cuda_runtime.h>
#include <cuda_bf16.h>
#include <cuda_fp16.h>
#include <cstdint>

// Problem constants
#define BATCH   8
#define SEQ     1024
#define DIM     768
#define HEADS   12
#define HDIM    64
#define INNER   768
#define TRIPLE  2304
#define SCALE   0.125f

typedef __nv_bfloat16 bf16;
typedef __half f16;

// ---------------- static scratch ----------------
__device__ __align__(128) f16 g_e[(size_t)BATCH * HEADS * SEQ * SEQ];   // E = exp(S)/16
__device__ __align__(128) f16 g_rinv[(size_t)BATCH * SEQ * SEQ];        // 1/sum_h E

__device__ __align__(128) f16 g_xh16[BATCH * SEQ * DIM];
__device__ __align__(128) f16 g_xl16[BATCH * SEQ * DIM];
__device__ __align__(128) f16 g_wq16[TRIPLE * DIM];     // transposed, hi only
__device__ __align__(128) f16 g_wo16[DIM * INNER];      // transposed, hi only
__device__ __align__(128) f16 g_oh16[BATCH * SEQ * INNER];
__device__ __align__(128) f16 g_ol16[BATCH * SEQ * INNER];

__device__ __align__(128) f16 g_qh16[BATCH * HEADS * SEQ * HDIM];
__device__ __align__(128) f16 g_ql16[BATCH * HEADS * SEQ * HDIM];
__device__ __align__(128) f16 g_kh16[BATCH * HEADS * SEQ * HDIM];
__device__ __align__(128) f16 g_vh16[BATCH * HEADS * SEQ * HDIM];
__device__ __align__(128) f16 g_vl16[BATCH * HEADS * SEQ * HDIM];

// ================= helpers =================
__device__ __forceinline__ uint32_t smem_to_u32(const void* p) {
    uint32_t a;
    asm("{ .reg .u64 t; cvta.to.shared.u64 t, %1; cvt.u32.u64 %0, t; }"
        : "=r"(a) : "l"(p));
    return a;
}
// swizzled byte offset within a [rows x 32 elems(16b)] tile (64B per row)
__device__ __forceinline__ uint32_t swz(uint32_t r, uint32_t c) {
    return (r * 4 + (c ^ ((r >> 1) & 3))) * 16;
}
__device__ __forceinline__ void ldmatrix_x4(uint32_t& r0, uint32_t& r1,
                                            uint32_t& r2, uint32_t& r3,
                                            uint32_t addr) {
    asm volatile("ldmatrix.sync.aligned.m8n8.x4.shared.b16 {%0,%1,%2,%3}, [%4];"
                 : "=r"(r0), "=r"(r1), "=r"(r2), "=r"(r3) : "r"(addr));
}
__device__ __forceinline__ void ldmatrix_x4_trans(uint32_t& r0, uint32_t& r1,
                                                  uint32_t& r2, uint32_t& r3,
                                                  uint32_t addr) {
    asm volatile("ldmatrix.sync.aligned.m8n8.x4.trans.shared.b16 {%0,%1,%2,%3}, [%4];"
                 : "=r"(r0), "=r"(r1), "=r"(r2), "=r"(r3) : "r"(addr));
}
__device__ __forceinline__ void mma_f16(float* c, const uint32_t* a,
                                        uint32_t b0, uint32_t b1) {
    asm volatile("mma.sync.aligned.m16n8k16.row.col.f32.f16.f16.f32 "
                 "{%0,%1,%2,%3}, {%4,%5,%6,%7}, {%8,%9}, {%0,%1,%2,%3};"
                 : "+f"(c[0]), "+f"(c[1]), "+f"(c[2]), "+f"(c[3])
                 : "r"(a[0]), "r"(a[1]), "r"(a[2]), "r"(a[3]),
                   "r"(b0), "r"(b1));
}
__device__ __forceinline__ uint32_t hmul2u(uint32_t a, uint32_t b) {
    __half2 r = __hmul2(*(__half2*)&a, *(__half2*)&b);
    return *(uint32_t*)&r;
}
#define CP_ASYNC16(sa, g) \
    asm volatile("cp.async.cg.shared.global [%0], [%1], 16;" :: "r"(sa), "l"(g))
#define CP_COMMIT() asm volatile("cp.async.commit_group;" ::: "memory")
#define CP_WAIT2()  asm volatile("cp.async.wait_group 2;" ::: "memory")
#define CP_WAIT1()  asm volatile("cp.async.wait_group 1;" ::: "memory")
#define CP_WAIT0()  asm volatile("cp.async.wait_group 0;" ::: "memory")

__device__ __forceinline__ float fast_exp_s(float x) {
    const float LOG2E = 1.4426950408889634f;
    const float MAGIC = 12582912.0f;
    float z = fmaf(x, LOG2E, MAGIC);
    int   e = __float_as_int(z) - 0x4B400000;
    float i = z - MAGIC;
    float f = fmaf(x, LOG2E, -i);
    float p = 1.5403531e-4f;
    p = fmaf(p, f, 1.3333558e-3f);
    p = fmaf(p, f, 9.6181291e-3f);
    p = fmaf(p, f, 5.5504109e-2f);
    p = fmaf(p, f, 2.4022651e-1f);
    p = fmaf(p, f, 6.9314718e-1f);
    p = fmaf(p, f, 1.0f);
    return __int_as_float(__float_as_int(p) + ((e - 4) << 23));
}
__device__ __forceinline__ void split2h(float2 v, __half2& h, __half2& l) {
    f16 hx = __float2half_rn(v.x), hy = __float2half_rn(v.y);
    h = __half2(hx, hy);
    l = __half2(__float2half_rn(v.x - __half2float(hx)),
                __float2half_rn(v.y - __half2float(hy)));
}

// =========================================================================
// Prep kernels
// =========================================================================
__global__ __launch_bounds__(256) void split_f16_kernel(
    const float* __restrict__ in, f16* __restrict__ hi, f16* __restrict__ lo, int n4)
{
    int i = blockIdx.x * 256 + threadIdx.x;
    if (i >= n4) return;
    float4 v = ((const float4*)in)[i];
    __half2 h0, l0, h1, l1;
    split2h(make_float2(v.x, v.y), h0, l0);
    split2h(make_float2(v.z, v.w), h1, l1);
    __half2* H = (__half2*)hi;
    __half2* L = (__half2*)lo;
    H[2 * i] = h0; H[2 * i + 1] = h1;
    L[2 * i] = l0; L[2 * i + 1] = l1;
}

__global__ __launch_bounds__(256) void transpose_f16_kernel(
    const float* __restrict__ in, f16* __restrict__ outp, int R, int C)
{
    __shared__ float t[32][33];
    const int tx = threadIdx.x, ty = threadIdx.y;
    const int bx = blockIdx.x, by = blockIdx.y;
    #pragma unroll
    for (int i = 0; i < 4; i++) {
        int r = by * 32 + ty + i * 8;
        t[ty + i * 8][tx] = in[(size_t)r * C + bx * 32 + tx];
    }
    __syncthreads();
    #pragma unroll
    for (int i = 0; i < 4; i++) {
        int c = bx * 32 + ty + i * 8;
        int r = by * 32 + tx;
        outp[(size_t)c * R + r] = __float2half_rn(t[tx][ty + i * 8]);
    }
}

// =========================================================================
// fp16 2-MMA GEMM: C = (Ah+Al) @ Bw^T. 128x128x32, 4-stage, 1 barrier/iter.
// =========================================================================
#define MAT_BYTES  8192
#define STG_BYTES  (3 * MAT_BYTES)
#define HM_STAGES  4
#define HM_SMEM_BYTES (HM_STAGES * STG_BYTES)   // 98304

__global__ __launch_bounds__(256, 2) void hmma_f16_gemm_kernel(
    const f16* __restrict__ Ah, const f16* __restrict__ Al,
    const f16* __restrict__ Bw,
    const float* __restrict__ bias, float* __restrict__ outp, int mode)
{
    extern __shared__ f16 sm[];
    const int tid = threadIdx.x, lane = tid & 31, wid = tid >> 5;
    const int wr = wid >> 1, wc = wid & 1;
    const int bn = blockIdx.x * 128, bm = blockIdx.y * 128;
    const uint32_t smem_base = smem_to_u32(sm);

    const f16* srcs[3] = {Ah, Al, Bw};
    const int rb[3] = {bm, bm, bn};

    float acc[2][8][4] = {};

    const int lr0 = tid >> 2, lr1 = (tid + 256) >> 2;
    const int lc = tid & 3;

    auto issue = [&](int it, int s) {
        const int k0 = it * 32;
        const uint32_t sb = smem_base + (uint32_t)(s * STG_BYTES);
        #pragma unroll
        for (int m = 0; m < 3; m++) {
            const f16* src = srcs[m];
            CP_ASYNC16(sb + m * MAT_BYTES + swz(lr0, lc),
                       src + (size_t)(rb[m] + lr0) * DIM + k0 + lc * 8);
            CP_ASYNC16(sb + m * MAT_BYTES + swz(lr1, lc),
                       src + (size_t)(rb[m] + lr1) * DIM + k0 + lc * 8);
        }
        CP_COMMIT();
    };

    const int NIT = DIM / 32;   // 24
    issue(0, 0);
    issue(1, 1);
    issue(2, 2);

    for (int it = 0; it < NIT; ++it) {
        if (it + 2 < NIT)      { CP_WAIT2(); }
        else if (it + 1 < NIT) { CP_WAIT1(); }
        else                   { CP_WAIT0(); }
        __syncthreads();
        if (it + 3 < NIT) issue(it + 3, (it + 3) % HM_STAGES);

        const uint32_t sb = smem_base + (uint32_t)((it % HM_STAGES) * STG_BYTES);
        #pragma unroll
        for (int ks = 0; ks < 2; ks++) {
            const uint32_t c0 = ks * 2 + (lane >> 4);
            uint32_t ah[2][4], al[2][4], bf[4][4];
            #pragma unroll
            for (int mt = 0; mt < 2; mt++) {
                uint32_t r = wr * 32 + mt * 16 + (lane & 15);
                ldmatrix_x4(ah[mt][0], ah[mt][1], ah[mt][2], ah[mt][3],
                            sb + 0 * MAT_BYTES + swz(r, c0));
                ldmatrix_x4(al[mt][0], al[mt][1], al[mt][2], al[mt][3],
                            sb + 1 * MAT_BYTES + swz(r, c0));
            }
            #pragma unroll
            for (int p = 0; p < 4; p++) {
                uint32_t r = wc * 64 + p * 16 + (lane & 15);
                ldmatrix_x4(bf[p][0], bf[p][1], bf[p][2], bf[p][3],
                            sb + 2 * MAT_BYTES + swz(r, c0));
            }
            #pragma unroll
            for (int p = 0; p < 4; p++)
                #pragma unroll
                for (int mt = 0; mt < 2; mt++) {
                    mma_f16(acc[mt][2 * p + 0], ah[mt], bf[p][0], bf[p][2]);
                    mma_f16(acc[mt][2 * p + 1], ah[mt], bf[p][1], bf[p][3]);
                }
            #pragma unroll
            for (int p = 0; p < 4; p++)
                #pragma unroll
                for (int mt = 0; mt < 2; mt++) {
                    mma_f16(acc[mt][2 * p + 0], al[mt], bf[p][0], bf[p][2]);
                    mma_f16(acc[mt][2 * p + 1], al[mt], bf[p][1], bf[p][3]);
                }
        }
    }

    // ---- epilogue ----
    #pragma unroll
    for (int mt = 0; mt < 2; mt++) {
        const int r = bm + wr * 32 + mt * 16 + (lane >> 2);
        #pragma unroll
        for (int nt = 0; nt < 8; nt++) {
            const int c = bn + wc * 64 + nt * 8 + 2 * (lane & 3);
            float2 v0 = make_float2(acc[mt][nt][0], acc[mt][nt][1]);
            float2 v1 = make_float2(acc[mt][nt][2], acc[mt][nt][3]);
            if (mode == 0) {
                int chunk = c / INNER;
                int e = c % INNER;
                int h = e >> 6, d = e & 63;
                int b0 = r >> 10, n0 = r & 1023;
                int r2 = r + 8;
                int b1 = r2 >> 10, n1 = r2 & 1023;
                size_t i0 = (((size_t)(b0 * HEADS + h) * SEQ) + n0) * HDIM + d;
                size_t i1 = (((size_t)(b1 * HEADS + h) * SEQ) + n1) * HDIM + d;
                if (chunk == 2) {
                    __half2 hh, ll;
                    split2h(v0, hh, ll);
                    *(__half2*)&g_vh16[i0] = hh;
                    *(__half2*)&g_vl16[i0] = ll;
                    split2h(v1, hh, ll);
                    *(__half2*)&g_vh16[i1] = hh;
                    *(__half2*)&g_vl16[i1] = ll;
                } else if (chunk == 0) {
                    v0.x *= SCALE; v0.y *= SCALE;
                    v1.x *= SCALE; v1.y *= SCALE;
                    __half2 hh, ll;
                    split2h(v0, hh, ll);
                    *(__half2*)&g_qh16[i0] = hh;
                    *(__half2*)&g_ql16[i0] = ll;
                    split2h(v1, hh, ll);
                    *(__half2*)&g_qh16[i1] = hh;
                    *(__half2*)&g_ql16[i1] = ll;
                } else {
                    *(__half2*)&g_kh16[i0] = __floats2half2_rn(v0.x, v0.y);
                    *(__half2*)&g_kh16[i1] = __floats2half2_rn(v1.x, v1.y);
                }
            } else {
                float2 bq = *(const float2*)&bias[c];
                v0.x += bq.x; v0.y += bq.y;
                v1.x += bq.x; v1.y += bq.y;
                *(float2*)&outp[(size_t)r * DIM + c] = v0;
                *(float2*)&outp[(size_t)(r + 8) * DIM + c] = v1;
            }
        }
    }
}

// =========================================================================
// Score v3: one CTA per (b, n0, m0) covers ALL 12 heads.
// Tile 128(n) x 64(m). Per head: load Qh/Ql (128x64) + Kh (64x64) via
// 2-stage cp.async; compute S, write E = exp(S)/16; accumulate head-sum
// in fp32 registers. After the loop, write rinv = 1/sum directly.
// Eliminates the separate sum kernel and its 201 MB E re-read.
// =========================================================================
#define SGS 72
#define S3_Q_BYTES (128 * SGS * 2)                 // 18432
#define S3_K_BYTES (64 * SGS * 2)                  // 9216
#define S3_STG (2 * S3_Q_BYTES + S3_K_BYTES)       // 46080
#define S3_SMEM_BYTES (2 * S3_STG)                 // 92160

__global__ __launch_bounds__(256, 2) void score_hmma_kernel()
{
    extern __shared__ f16 smh[];
    const int tid = threadIdx.x, lane = tid & 31, wid = tid >> 5;
    const int wr = wid >> 1, wc = wid & 1;     // wr: 4 n-rows of 32, wc: 2 m-cols of 32
    const int m0 = blockIdx.x * 64;
    const int n0 = blockIdx.y * 128;
    const int b  = blockIdx.z;
    const uint32_t smem_base = smem_to_u32(smh);

    auto issue = [&](int h, int s) {
        const size_t bh = (size_t)(b * HEADS + h);
        const f16* qh = g_qh16 + (bh * SEQ + n0) * HDIM;
        const f16* ql = g_ql16 + (bh * SEQ + n0) * HDIM;
        const f16* kh = g_kh16 + (bh * SEQ + m0) * HDIM;
        const uint32_t sb = smem_base + (uint32_t)(s * S3_STG);
        #pragma unroll
        for (int t = 0; t < 4; t++) {
            int i = tid + t * 256;
            int row = i >> 3, ch = i & 7;
            uint32_t doff = (uint32_t)(row * SGS + ch * 8) * 2;
            CP_ASYNC16(sb + doff, qh + (size_t)row * HDIM + ch * 8);
            CP_ASYNC16(sb + S3_Q_BYTES + doff, ql + (size_t)row * HDIM + ch * 8);
        }
        #pragma unroll
        for (int t = 0; t < 2; t++) {
            int i = tid + t * 256;
            int row = i >> 3, ch = i & 7;
            CP_ASYNC16(sb + 2 * S3_Q_BYTES + (uint32_t)(row * SGS + ch * 8) * 2,
                       kh + (size_t)row * HDIM + ch * 8);
        }
        CP_COMMIT();
    };

    issue(0, 0);
    issue(1, 1);

    float sumf[2][4][4] = {};

    for (int h = 0; h < HEADS; ++h) {
        if (h + 1 < HEADS) { CP_WAIT1(); } else { CP_WAIT0(); }
        __syncthreads();

        const uint32_t sb = smem_base + (uint32_t)((h & 1) * S3_STG);
        const uint32_t kbse = sb + 2 * S3_Q_BYTES;

        float acc[2][4][4] = {};
        #pragma unroll
        for (int ks = 0; ks < 4; ks++) {
            const uint32_t col = ks * 16 + (lane >> 4) * 8;
            uint32_t ah[2][4], al[2][4], bf[2][4];
            #pragma unroll
            for (int mt = 0; mt < 2; mt++) {
                uint32_t r = wr * 32 + mt * 16 + (lane & 15);
                ldmatrix_x4(ah[mt][0], ah[mt][1], ah[mt][2], ah[mt][3],
                            sb + (r * SGS + col) * 2);
                ldmatrix_x4(al[mt][0], al[mt][1], al[mt][2], al[mt][3],
                            sb + S3_Q_BYTES + (r * SGS + col) * 2);
            }
            #pragma unroll
            for (int p = 0; p < 2; p++) {
                uint32_t r = wc * 32 + p * 16 + (lane & 15);
                ldmatrix_x4(bf[p][0], bf[p][1], bf[p][2], bf[p][3],
                            kbse + (r * SGS + col) * 2);
            }
            #pragma unroll
            for (int p = 0; p < 2; p++)
                #pragma unroll
                for (int mt = 0; mt < 2; mt++) {
                    mma_f16(acc[mt][2 * p + 0], ah[mt], bf[p][0], bf[p][2]);
                    mma_f16(acc[mt][2 * p + 1], ah[mt], bf[p][1], bf[p][3]);
                }
            #pragma unroll
            for (int p = 0; p < 2; p++)
                #pragma unroll
                for (int mt = 0; mt < 2; mt++) {
                    mma_f16(acc[mt][2 * p + 0], al[mt], bf[p][0], bf[p][2]);
                    mma_f16(acc[mt][2 * p + 1], al[mt], bf[p][1], bf[p][3]);
                }
        }

        // epilogue: E for this head + accumulate head-sum (fp32)
        f16* ebase = g_e + ((size_t)(b * HEADS + h) * SEQ) * SEQ;
        #pragma unroll
        for (int mt = 0; mt < 2; mt++) {
            const int r = n0 + wr * 32 + mt * 16 + (lane >> 2);
            #pragma unroll
            for (int nt = 0; nt < 4; nt++) {
                const int c = m0 + wc * 32 + nt * 8 + 2 * (lane & 3);
                float e0 = fast_exp_s(acc[mt][nt][0]);
                float e1 = fast_exp_s(acc[mt][nt][1]);
                float e2 = fast_exp_s(acc[mt][nt][2]);
                float e3 = fast_exp_s(acc[mt][nt][3]);
                sumf[mt][nt][0] += e0; sumf[mt][nt][1] += e1;
                sumf[mt][nt][2] += e2; sumf[mt][nt][3] += e3;
                *(__half2*)&ebase[(size_t)r * SEQ + c] = __floats2half2_rn(e0, e1);
                *(__half2*)&ebase[(size_t)(r + 8) * SEQ + c] = __floats2half2_rn(e2, e3);
            }
        }

        __syncthreads();   // all warps done with stage before it is reloaded
        if (h + 2 < HEADS) issue(h + 2, h & 1);
    }

    // rinv epilogue
    #pragma unroll
    for (int mt = 0; mt < 2; mt++) {
        const int r = n0 + wr * 32 + mt * 16 + (lane >> 2);
        #pragma unroll
        for (int nt = 0; nt < 4; nt++) {
            const int c = m0 + wc * 32 + nt * 8 + 2 * (lane & 3);
            *(__half2*)&g_rinv[((size_t)(b * SEQ + r)) * SEQ + c] =
                __floats2half2_rn(1.0f / sumf[mt][nt][0], 1.0f / sumf[mt][nt][1]);
            *(__half2*)&g_rinv[((size_t)(b * SEQ + r + 8)) * SEQ + c] =
                __floats2half2_rn(1.0f / sumf[mt][nt][2], 1.0f / sumf[mt][nt][3]);
        }
    }
}

// =========================================================================
// AV HMMA (fp16): O = (E*rinv) @ V. Unchanged (occ-3 protected).
// =========================================================================
#define AVE_BYTES 8192
#define AVR_BYTES 8192
#define AVV_BYTES 4608
#define AV_STG_BYTES (AVE_BYTES + AVR_BYTES + 2 * AVV_BYTES)  // 25600
#define AV_SMEM_BYTES (3 * AV_STG_BYTES)                      // 76800
#define VGS 72

__global__ __launch_bounds__(256, 3) void av_hmma_kernel()
{
    extern __shared__ f16 smh[];
    const int tid = threadIdx.x, lane = tid & 31, wid = tid >> 5;
    const int wr = wid >> 1, wc = wid & 1;
    const int n0 = blockIdx.x * 128;
    const int bh = blockIdx.y;
    const int b = bh / HEADS, h = bh % HEADS;
    const uint32_t smem_base = smem_to_u32(smh);

    const f16* ep  = g_e    + ((size_t)bh * SEQ + n0) * SEQ;
    const f16* rp  = g_rinv + ((size_t)(b * SEQ + n0)) * SEQ;
    const f16* vhp = g_vh16 + (size_t)bh * SEQ * HDIM;
    const f16* vlp = g_vl16 + (size_t)bh * SEQ * HDIM;

    float acc[2][4][4] = {};

    const int lr0 = tid >> 2, lr1 = (tid + 256) >> 2;
    const int lc = tid & 3;
    const int vrow_ld = tid >> 3, vch_ld = tid & 7;

    auto issue = [&](int it, int s) {
        const int k0 = it * 32;
        const uint32_t sb = smem_base + (uint32_t)(s * AV_STG_BYTES);
        CP_ASYNC16(sb + swz(lr0, lc), ep + (size_t)lr0 * SEQ + k0 + lc * 8);
        CP_ASYNC16(sb + swz(lr1, lc), ep + (size_t)lr1 * SEQ + k0 + lc * 8);
        CP_ASYNC16(sb + AVE_BYTES + swz(lr0, lc), rp + (size_t)lr0 * SEQ + k0 + lc * 8);
        CP_ASYNC16(sb + AVE_BYTES + swz(lr1, lc), rp + (size_t)lr1 * SEQ + k0 + lc * 8);
        uint32_t doff = (uint32_t)(vrow_ld * VGS + vch_ld * 8) * 2;
        CP_ASYNC16(sb + AVE_BYTES + AVR_BYTES + doff,
                   vhp + (size_t)(k0 + vrow_ld) * HDIM + vch_ld * 8);
        CP_ASYNC16(sb + AVE_BYTES + AVR_BYTES + AVV_BYTES + doff,
                   vlp + (size_t)(k0 + vrow_ld) * HDIM + vch_ld * 8);
        CP_COMMIT();
    };

    const int NIT = SEQ / 32;
    issue(0, 0);
    issue(1, 1);

    for (int it = 0; it < NIT; ++it) {
        if (it + 1 < NIT) { CP_WAIT1(); } else { CP_WAIT0(); }
        __syncthreads();
        if (it + 2 < NIT) issue(it + 2, (it + 2) % 3);

        const uint32_t sb = smem_base + (uint32_t)((it % 3) * AV_STG_BYTES);
        const uint32_t rvb = sb + AVE_BYTES;
        const uint32_t vhb = rvb + AVR_BYTES;
        const uint32_t vlb = vhb + AVV_BYTES;

        #pragma unroll
        for (int ks = 0; ks < 2; ks++) {
            const uint32_t c0 = ks * 2 + (lane >> 4);
            uint32_t a[2][4];
            #pragma unroll
            for (int mt = 0; mt < 2; mt++) {
                uint32_t r = wr * 32 + mt * 16 + (lane & 15);
                uint32_t rv[4];
                ldmatrix_x4(a[mt][0], a[mt][1], a[mt][2], a[mt][3],
                            sb + swz(r, c0));
                ldmatrix_x4(rv[0], rv[1], rv[2], rv[3],
                            rvb + swz(r, c0));
                #pragma unroll
                for (int j = 0; j < 4; j++) a[mt][j] = hmul2u(a[mt][j], rv[j]);
            }
            const uint32_t kb = ks * 16;
            #pragma unroll
            for (int nb = 0; nb < 2; nb++) {
                const uint32_t d0 = wc * 32 + nb * 16;
                uint32_t vrow = kb + (lane & 7) + ((lane >> 3) & 1) * 8;
                uint32_t vcol = d0 + (lane >> 4) * 8;
                uint32_t bh0, bh1, bh2, bh3, bl0, bl1, bl2, bl3;
                ldmatrix_x4_trans(bh0, bh1, bh2, bh3, vhb + (vrow * VGS + vcol) * 2);
                ldmatrix_x4_trans(bl0, bl1, bl2, bl3, vlb + (vrow * VGS + vcol) * 2);
                const int nt0 = nb * 2, nt1 = nb * 2 + 1;
                #pragma unroll
                for (int mt = 0; mt < 2; mt++) {
                    mma_f16(acc[mt][nt0], a[mt], bh0, bh1);
                    mma_f16(acc[mt][nt1], a[mt], bh2, bh3);
                }
                #pragma unroll
                for (int mt = 0; mt < 2; mt++) {
                    mma_f16(acc[mt][nt0], a[mt], bl0, bl1);
                    mma_f16(acc[mt][nt1], a[mt], bl2, bl3);
                }
            }
        }
    }

    // epilogue: O -> fp16 hi/lo at [b, n, h*64+d]
    #pragma unroll
    for (int mt = 0; mt < 2; mt++) {
        const int r = n0 + wr * 32 + mt * 16 + (lane >> 2);
        #pragma unroll
        for (int nt = 0; nt < 4; nt++) {
            const int c = wc * 32 + nt * 8 + 2 * (lane & 3);
            float2 v0 = make_float2(acc[mt][nt][0], acc[mt][nt][1]);
            float2 v1 = make_float2(acc[mt][nt][2], acc[mt][nt][3]);
            __half2 hh, ll;
            size_t i0 = ((size_t)(b * SEQ + r)) * INNER + h * HDIM + c;
            split2h(v0, hh, ll);
            *(__half2*)&g_oh16[i0] = hh;
            *(__half2*)&g_ol16[i0] = ll;
            size_t i1 = ((size_t)(b * SEQ + r + 8)) * INNER + h * HDIM + c;
            split2h(v1, hh, ll);
            *(__half2*)&g_oh16[i1] = hh;
            *(__half2*)&g_ol16[i1] = ll;
        }
    }
}

// =========================================================================
extern "C" void kernel_launch(void* const* d_in, const int* in_sizes, int n_in,
                              void* d_out, int out_size)
{
    const float* x     = (const float*)d_in[0];
    const float* w_qkv = (const float*)d_in[1];
    const float* w_out = (const float*)d_in[2];
    const float* b_out = (const float*)d_in[3];
    float* out = (float*)d_out;

    cudaFuncSetAttribute(hmma_f16_gemm_kernel,
                         cudaFuncAttributeMaxDynamicSharedMemorySize, HM_SMEM_BYTES);
    cudaFuncSetAttribute(score_hmma_kernel,
                         cudaFuncAttributeMaxDynamicSharedMemorySize, S3_SMEM_BYTES);
    cudaFuncSetAttribute(av_hmma_kernel,
                         cudaFuncAttributeMaxDynamicSharedMemorySize, AV_SMEM_BYTES);

    f16 *xh, *xl, *wq, *wo, *oh, *ol;
    cudaGetSymbolAddress((void**)&xh, g_xh16);
    cudaGetSymbolAddress((void**)&xl, g_xl16);
    cudaGetSymbolAddress((void**)&wq, g_wq16);
    cudaGetSymbolAddress((void**)&wo, g_wo16);
    cudaGetSymbolAddress((void**)&oh, g_oh16);
    cudaGetSymbolAddress((void**)&ol, g_ol16);

    // Prep
    {
        int n4 = BATCH * SEQ * DIM / 4;
        split_f16_kernel<<<(n4 + 255) / 256, 256>>>(x, xh, xl, n4);
    }
    {
        dim3 grid(TRIPLE / 32, DIM / 32);
        transpose_f16_kernel<<<grid, dim3(32, 8)>>>(w_qkv, wq, DIM, TRIPLE);
    }
    {
        dim3 grid(DIM / 32, INNER / 32);
        transpose_f16_kernel<<<grid, dim3(32, 8)>>>(w_out, wo, INNER, DIM);
    }

    // K1: QKV projection (fp16 2-MMA, 4-stage)
    {
        dim3 grid(TRIPLE / 128, (BATCH * SEQ) / 128);
        hmma_f16_gemm_kernel<<<grid, 256, HM_SMEM_BYTES>>>(xh, xl, wq, nullptr, nullptr, 0);
    }
    // K2: scores + exp + head-sum -> E, rinv (fused; no separate sum kernel)
    {
        dim3 grid(SEQ / 64, SEQ / 128, BATCH);   // 16 x 8 x 8 = 1024
        score_hmma_kernel<<<grid, 256, S3_SMEM_BYTES>>>();
    }
    // K3: O = (E*rinv) @ V (fp16 HMMA)
    {
        dim3 grid(SEQ / 128, BATCH * HEADS);
        av_hmma_kernel<<<grid, 256, AV_SMEM_BYTES>>>();
    }
    // K4: output projection (fp16 2-MMA, 4-stage) + bias
    {
        dim3 grid(DIM / 128, (BATCH * SEQ) / 128);
        hmma_f16_gemm_kernel<<<grid, 256, HM_SMEM_BYTES>>>(oh, ol, wo, b_out, out, 1);
    }
}

// round 14
// speedup vs baseline: 1.1668x; 1.1277x over previous
#include <cuda_runtime.h>
#include <cuda_bf16.h>
#include <cuda_fp16.h>
#include <cstdint>

// Problem constants
#define BATCH   8
#define SEQ     1024
#define DIM     768
#define HEADS   12
#define HDIM    64
#define INNER   768
#define TRIPLE  2304
#define SCALE   0.125f

typedef __half f16;

// ---------------- static scratch ----------------
__device__ __align__(128) f16 g_e[(size_t)BATCH * HEADS * SEQ * SEQ];   // E = exp(S)/16
__device__ __align__(128) f16 g_rinv[(size_t)BATCH * SEQ * SEQ];        // 1/sum_h E

__device__ __align__(128) f16 g_xh16[BATCH * SEQ * DIM];
__device__ __align__(128) f16 g_xl16[BATCH * SEQ * DIM];
__device__ __align__(128) f16 g_wq16[TRIPLE * DIM];     // transposed, hi only
__device__ __align__(128) f16 g_wo16[DIM * INNER];      // transposed, hi only
__device__ __align__(128) f16 g_o16[BATCH * SEQ * INNER];   // attention out (single fp16)

__device__ __align__(128) f16 g_qh16[BATCH * HEADS * SEQ * HDIM];
__device__ __align__(128) f16 g_ql16[BATCH * HEADS * SEQ * HDIM];
__device__ __align__(128) f16 g_kh16[BATCH * HEADS * SEQ * HDIM];
__device__ __align__(128) f16 g_v16[BATCH * HEADS * SEQ * HDIM];    // V (single fp16)

// ================= helpers =================
__device__ __forceinline__ uint32_t smem_to_u32(const void* p) {
    uint32_t a;
    asm("{ .reg .u64 t; cvta.to.shared.u64 t, %1; cvt.u32.u64 %0, t; }"
        : "=r"(a) : "l"(p));
    return a;
}
// swizzled byte offset within a [rows x 32 elems(16b)] tile (64B per row)
__device__ __forceinline__ uint32_t swz(uint32_t r, uint32_t c) {
    return (r * 4 + (c ^ ((r >> 1) & 3))) * 16;
}
__device__ __forceinline__ void ldmatrix_x4(uint32_t& r0, uint32_t& r1,
                                            uint32_t& r2, uint32_t& r3,
                                            uint32_t addr) {
    asm volatile("ldmatrix.sync.aligned.m8n8.x4.shared.b16 {%0,%1,%2,%3}, [%4];"
                 : "=r"(r0), "=r"(r1), "=r"(r2), "=r"(r3) : "r"(addr));
}
__device__ __forceinline__ void ldmatrix_x4_trans(uint32_t& r0, uint32_t& r1,
                                                  uint32_t& r2, uint32_t& r3,
                                                  uint32_t addr) {
    asm volatile("ldmatrix.sync.aligned.m8n8.x4.trans.shared.b16 {%0,%1,%2,%3}, [%4];"
                 : "=r"(r0), "=r"(r1), "=r"(r2), "=r"(r3) : "r"(addr));
}
__device__ __forceinline__ void mma_f16(float* c, const uint32_t* a,
                                        uint32_t b0, uint32_t b1) {
    asm volatile("mma.sync.aligned.m16n8k16.row.col.f32.f16.f16.f32 "
                 "{%0,%1,%2,%3}, {%4,%5,%6,%7}, {%8,%9}, {%0,%1,%2,%3};"
                 : "+f"(c[0]), "+f"(c[1]), "+f"(c[2]), "+f"(c[3])
                 : "r"(a[0]), "r"(a[1]), "r"(a[2]), "r"(a[3]),
                   "r"(b0), "r"(b1));
}
__device__ __forceinline__ uint32_t hmul2u(uint32_t a, uint32_t b) {
    __half2 r = __hmul2(*(__half2*)&a, *(__half2*)&b);
    return *(uint32_t*)&r;
}
#define CP_ASYNC16(sa, g) \
    asm volatile("cp.async.cg.shared.global [%0], [%1], 16;" :: "r"(sa), "l"(g))
#define CP_COMMIT() asm volatile("cp.async.commit_group;" ::: "memory")
#define CP_WAIT2()  asm volatile("cp.async.wait_group 2;" ::: "memory")
#define CP_WAIT1()  asm volatile("cp.async.wait_group 1;" ::: "memory")
#define CP_WAIT0()  asm volatile("cp.async.wait_group 0;" ::: "memory")

__device__ __forceinline__ float fast_exp_s(float x) {
    const float LOG2E = 1.4426950408889634f;
    const float MAGIC = 12582912.0f;
    float z = fmaf(x, LOG2E, MAGIC);
    int   e = __float_as_int(z) - 0x4B400000;
    float i = z - MAGIC;
    float f = fmaf(x, LOG2E, -i);
    float p = 1.5403531e-4f;
    p = fmaf(p, f, 1.3333558e-3f);
    p = fmaf(p, f, 9.6181291e-3f);
    p = fmaf(p, f, 5.5504109e-2f);
    p = fmaf(p, f, 2.4022651e-1f);
    p = fmaf(p, f, 6.9314718e-1f);
    p = fmaf(p, f, 1.0f);
    return __int_as_float(__float_as_int(p) + ((e - 4) << 23));
}
__device__ __forceinline__ void split2h(float2 v, __half2& h, __half2& l) {
    f16 hx = __float2half_rn(v.x), hy = __float2half_rn(v.y);
    h = __half2(hx, hy);
    l = __half2(__float2half_rn(v.x - __half2float(hx)),
                __float2half_rn(v.y - __half2float(hy)));
}

// =========================================================================
// Prep kernels
// =========================================================================
__global__ __launch_bounds__(256) void split_f16_kernel(
    const float* __restrict__ in, f16* __restrict__ hi, f16* __restrict__ lo, int n4)
{
    int i = blockIdx.x * 256 + threadIdx.x;
    if (i >= n4) return;
    float4 v = ((const float4*)in)[i];
    __half2 h0, l0, h1, l1;
    split2h(make_float2(v.x, v.y), h0, l0);
    split2h(make_float2(v.z, v.w), h1, l1);
    __half2* H = (__half2*)hi;
    __half2* L = (__half2*)lo;
    H[2 * i] = h0; H[2 * i + 1] = h1;
    L[2 * i] = l0; L[2 * i + 1] = l1;
}

__global__ __launch_bounds__(256) void transpose_f16_kernel(
    const float* __restrict__ in, f16* __restrict__ outp, int R, int C)
{
    __shared__ float t[32][33];
    const int tx = threadIdx.x, ty = threadIdx.y;
    const int bx = blockIdx.x, by = blockIdx.y;
    #pragma unroll
    for (int i = 0; i < 4; i++) {
        int r = by * 32 + ty + i * 8;
        t[ty + i * 8][tx] = in[(size_t)r * C + bx * 32 + tx];
    }
    __syncthreads();
    #pragma unroll
    for (int i = 0; i < 4; i++) {
        int c = bx * 32 + ty + i * 8;
        int r = by * 32 + tx;
        outp[(size_t)c * R + r] = __float2half_rn(t[tx][ty + i * 8]);
    }
}

// =========================================================================
// fp16 GEMM: C = (Ah [+Al]) @ Bw^T. 128x128x32, 4-stage, 1 barrier/iter.
// TWO_A=true: hi/lo A (2-MMA); false: single A (1-MMA).
// mode 0: qkv epilogue; mode 1: oproj + bias -> fp32 out.
// =========================================================================
#define MAT_BYTES  8192
#define HM_STAGES  4

template<bool TWO_A>
__global__ __launch_bounds__(256, 2) void hmma_f16_gemm_kernel(
    const f16* __restrict__ Ah, const f16* __restrict__ Al,
    const f16* __restrict__ Bw,
    const float* __restrict__ bias, float* __restrict__ outp, int mode)
{
    constexpr int NMAT = TWO_A ? 3 : 2;
    constexpr uint32_t STG = NMAT * MAT_BYTES;
    constexpr uint32_t BOFF = (NMAT - 1) * MAT_BYTES;

    extern __shared__ f16 sm[];
    const int tid = threadIdx.x, lane = tid & 31, wid = tid >> 5;
    const int wr = wid >> 1, wc = wid & 1;
    const int bn = blockIdx.x * 128, bm = blockIdx.y * 128;
    const uint32_t smem_base = smem_to_u32(sm);

    const f16* srcs[3] = {Ah, TWO_A ? Al : Bw, Bw};
    const int rb[3] = {bm, TWO_A ? bm : bn, bn};

    float acc[2][8][4] = {};

    const int lr0 = tid >> 2, lr1 = (tid + 256) >> 2;
    const int lc = tid & 3;

    auto issue = [&](int it, int s) {
        const int k0 = it * 32;
        const uint32_t sb = smem_base + (uint32_t)s * STG;
        #pragma unroll
        for (int m = 0; m < NMAT; m++) {
            const f16* src = srcs[m];
            CP_ASYNC16(sb + m * MAT_BYTES + swz(lr0, lc),
                       src + (size_t)(rb[m] + lr0) * DIM + k0 + lc * 8);
            CP_ASYNC16(sb + m * MAT_BYTES + swz(lr1, lc),
                       src + (size_t)(rb[m] + lr1) * DIM + k0 + lc * 8);
        }
        CP_COMMIT();
    };

    const int NIT = DIM / 32;   // 24
    issue(0, 0);
    issue(1, 1);
    issue(2, 2);

    for (int it = 0; it < NIT; ++it) {
        if (it + 2 < NIT)      { CP_WAIT2(); }
        else if (it + 1 < NIT) { CP_WAIT1(); }
        else                   { CP_WAIT0(); }
        __syncthreads();
        if (it + 3 < NIT) issue(it + 3, (it + 3) % HM_STAGES);

        const uint32_t sb = smem_base + (uint32_t)((it % HM_STAGES) * STG);
        #pragma unroll
        for (int ks = 0; ks < 2; ks++) {
            const uint32_t c0 = ks * 2 + (lane >> 4);
            uint32_t ah[2][4], al[2][4], bf[4][4];
            #pragma unroll
            for (int mt = 0; mt < 2; mt++) {
                uint32_t r = wr * 32 + mt * 16 + (lane & 15);
                ldmatrix_x4(ah[mt][0], ah[mt][1], ah[mt][2], ah[mt][3],
                            sb + 0 * MAT_BYTES + swz(r, c0));
                if (TWO_A)
                    ldmatrix_x4(al[mt][0], al[mt][1], al[mt][2], al[mt][3],
                                sb + 1 * MAT_BYTES + swz(r, c0));
            }
            #pragma unroll
            for (int p = 0; p < 4; p++) {
                uint32_t r = wc * 64 + p * 16 + (lane & 15);
                ldmatrix_x4(bf[p][0], bf[p][1], bf[p][2], bf[p][3],
                            sb + BOFF + swz(r, c0));
            }
            #pragma unroll
            for (int p = 0; p < 4; p++)
                #pragma unroll
                for (int mt = 0; mt < 2; mt++) {
                    mma_f16(acc[mt][2 * p + 0], ah[mt], bf[p][0], bf[p][2]);
                    mma_f16(acc[mt][2 * p + 1], ah[mt], bf[p][1], bf[p][3]);
                }
            if (TWO_A) {
                #pragma unroll
                for (int p = 0; p < 4; p++)
                    #pragma unroll
                    for (int mt = 0; mt < 2; mt++) {
                        mma_f16(acc[mt][2 * p + 0], al[mt], bf[p][0], bf[p][2]);
                        mma_f16(acc[mt][2 * p + 1], al[mt], bf[p][1], bf[p][3]);
                    }
            }
        }
    }

    // ---- epilogue ----
    #pragma unroll
    for (int mt = 0; mt < 2; mt++) {
        const int r = bm + wr * 32 + mt * 16 + (lane >> 2);
        #pragma unroll
        for (int nt = 0; nt < 8; nt++) {
            const int c = bn + wc * 64 + nt * 8 + 2 * (lane & 3);
            float2 v0 = make_float2(acc[mt][nt][0], acc[mt][nt][1]);
            float2 v1 = make_float2(acc[mt][nt][2], acc[mt][nt][3]);
            if (mode == 0) {
                int chunk = c / INNER;
                int e = c % INNER;
                int h = e >> 6, d = e & 63;
                int b0 = r >> 10, n0 = r & 1023;
                int r2 = r + 8;
                int b1 = r2 >> 10, n1 = r2 & 1023;
                size_t i0 = (((size_t)(b0 * HEADS + h) * SEQ) + n0) * HDIM + d;
                size_t i1 = (((size_t)(b1 * HEADS + h) * SEQ) + n1) * HDIM + d;
                if (chunk == 2) {
                    // V: single fp16
                    *(__half2*)&g_v16[i0] = __floats2half2_rn(v0.x, v0.y);
                    *(__half2*)&g_v16[i1] = __floats2half2_rn(v1.x, v1.y);
                } else if (chunk == 0) {
                    v0.x *= SCALE; v0.y *= SCALE;
                    v1.x *= SCALE; v1.y *= SCALE;
                    __half2 hh, ll;
                    split2h(v0, hh, ll);
                    *(__half2*)&g_qh16[i0] = hh;
                    *(__half2*)&g_ql16[i0] = ll;
                    split2h(v1, hh, ll);
                    *(__half2*)&g_qh16[i1] = hh;
                    *(__half2*)&g_ql16[i1] = ll;
                } else {
                    *(__half2*)&g_kh16[i0] = __floats2half2_rn(v0.x, v0.y);
                    *(__half2*)&g_kh16[i1] = __floats2half2_rn(v1.x, v1.y);
                }
            } else {
                float2 bq = *(const float2*)&bias[c];
                v0.x += bq.x; v0.y += bq.y;
                v1.x += bq.x; v1.y += bq.y;
                *(float2*)&outp[(size_t)r * DIM + c] = v0;
                *(float2*)&outp[(size_t)(r + 8) * DIM + c] = v1;
            }
        }
    }
}

// =========================================================================
// Score (fused): one CTA per (b, n0, m0), all 12 heads; writes E and rinv.
// =========================================================================
#define SGS 72
#define S3_Q_BYTES (128 * SGS * 2)                 // 18432
#define S3_K_BYTES (64 * SGS * 2)                  // 9216
#define S3_STG (2 * S3_Q_BYTES + S3_K_BYTES)       // 46080
#define S3_SMEM_BYTES (2 * S3_STG)                 // 92160

__global__ __launch_bounds__(256, 2) void score_hmma_kernel()
{
    extern __shared__ f16 smh[];
    const int tid = threadIdx.x, lane = tid & 31, wid = tid >> 5;
    const int wr = wid >> 1, wc = wid & 1;
    const int m0 = blockIdx.x * 64;
    const int n0 = blockIdx.y * 128;
    const int b  = blockIdx.z;
    const uint32_t smem_base = smem_to_u32(smh);

    auto issue = [&](int h, int s) {
        const size_t bh = (size_t)(b * HEADS + h);
        const f16* qh = g_qh16 + (bh * SEQ + n0) * HDIM;
        const f16* ql = g_ql16 + (bh * SEQ + n0) * HDIM;
        const f16* kh = g_kh16 + (bh * SEQ + m0) * HDIM;
        const uint32_t sb = smem_base + (uint32_t)(s * S3_STG);
        #pragma unroll
        for (int t = 0; t < 4; t++) {
            int i = tid + t * 256;
            int row = i >> 3, ch = i & 7;
            uint32_t doff = (uint32_t)(row * SGS + ch * 8) * 2;
            CP_ASYNC16(sb + doff, qh + (size_t)row * HDIM + ch * 8);
            CP_ASYNC16(sb + S3_Q_BYTES + doff, ql + (size_t)row * HDIM + ch * 8);
        }
        #pragma unroll
        for (int t = 0; t < 2; t++) {
            int i = tid + t * 256;
            int row = i >> 3, ch = i & 7;
            CP_ASYNC16(sb + 2 * S3_Q_BYTES + (uint32_t)(row * SGS + ch * 8) * 2,
                       kh + (size_t)row * HDIM + ch * 8);
        }
        CP_COMMIT();
    };

    issue(0, 0);
    issue(1, 1);

    float sumf[2][4][4] = {};

    for (int h = 0; h < HEADS; ++h) {
        if (h + 1 < HEADS) { CP_WAIT1(); } else { CP_WAIT0(); }
        __syncthreads();

        const uint32_t sb = smem_base + (uint32_t)((h & 1) * S3_STG);
        const uint32_t kbse = sb + 2 * S3_Q_BYTES;

        float acc[2][4][4] = {};
        #pragma unroll
        for (int ks = 0; ks < 4; ks++) {
            const uint32_t col = ks * 16 + (lane >> 4) * 8;
            uint32_t ah[2][4], al[2][4], bf[2][4];
            #pragma unroll
            for (int mt = 0; mt < 2; mt++) {
                uint32_t r = wr * 32 + mt * 16 + (lane & 15);
                ldmatrix_x4(ah[mt][0], ah[mt][1], ah[mt][2], ah[mt][3],
                            sb + (r * SGS + col) * 2);
                ldmatrix_x4(al[mt][0], al[mt][1], al[mt][2], al[mt][3],
                            sb + S3_Q_BYTES + (r * SGS + col) * 2);
            }
            #pragma unroll
            for (int p = 0; p < 2; p++) {
                uint32_t r = wc * 32 + p * 16 + (lane & 15);
                ldmatrix_x4(bf[p][0], bf[p][1], bf[p][2], bf[p][3],
                            kbse + (r * SGS + col) * 2);
            }
            #pragma unroll
            for (int p = 0; p < 2; p++)
                #pragma unroll
                for (int mt = 0; mt < 2; mt++) {
                    mma_f16(acc[mt][2 * p + 0], ah[mt], bf[p][0], bf[p][2]);
                    mma_f16(acc[mt][2 * p + 1], ah[mt], bf[p][1], bf[p][3]);
                }
            #pragma unroll
            for (int p = 0; p < 2; p++)
                #pragma unroll
                for (int mt = 0; mt < 2; mt++) {
                    mma_f16(acc[mt][2 * p + 0], al[mt], bf[p][0], bf[p][2]);
                    mma_f16(acc[mt][2 * p + 1], al[mt], bf[p][1], bf[p][3]);
                }
        }

        // epilogue: E for this head + accumulate head-sum (fp32)
        f16* ebase = g_e + ((size_t)(b * HEADS + h) * SEQ) * SEQ;
        #pragma unroll
        for (int mt = 0; mt < 2; mt++) {
            const int r = n0 + wr * 32 + mt * 16 + (lane >> 2);
            #pragma unroll
            for (int nt = 0; nt < 4; nt++) {
                const int c = m0 + wc * 32 + nt * 8 + 2 * (lane & 3);
                float e0 = fast_exp_s(acc[mt][nt][0]);
                float e1 = fast_exp_s(acc[mt][nt][1]);
                float e2 = fast_exp_s(acc[mt][nt][2]);
                float e3 = fast_exp_s(acc[mt][nt][3]);
                sumf[mt][nt][0] += e0; sumf[mt][nt][1] += e1;
                sumf[mt][nt][2] += e2; sumf[mt][nt][3] += e3;
                *(__half2*)&ebase[(size_t)r * SEQ + c] = __floats2half2_rn(e0, e1);
                *(__half2*)&ebase[(size_t)(r + 8) * SEQ + c] = __floats2half2_rn(e2, e3);
            }
        }

        __syncthreads();
        if (h + 2 < HEADS) issue(h + 2, h & 1);
    }

    // rinv epilogue
    #pragma unroll
    for (int mt = 0; mt < 2; mt++) {
        const int r = n0 + wr * 32 + mt * 16 + (lane >> 2);
        #pragma unroll
        for (int nt = 0; nt < 4; nt++) {
            const int c = m0 + wc * 32 + nt * 8 + 2 * (lane & 3);
            *(__half2*)&g_rinv[((size_t)(b * SEQ + r)) * SEQ + c] =
                __floats2half2_rn(1.0f / sumf[mt][nt][0], 1.0f / sumf[mt][nt][1]);
            *(__half2*)&g_rinv[((size_t)(b * SEQ + r + 8)) * SEQ + c] =
                __floats2half2_rn(1.0f / sumf[mt][nt][2], 1.0f / sumf[mt][nt][3]);
        }
    }
}

// =========================================================================
// AV HMMA (fp16): O = (E*rinv) @ V, V single fp16 (1 MMA pass).
// =========================================================================
#define AVE_BYTES 8192
#define AVR_BYTES 8192
#define AVV_BYTES 4608
#define AV_STG_BYTES (AVE_BYTES + AVR_BYTES + AVV_BYTES)   // 20992
#define AV_SMEM_BYTES (3 * AV_STG_BYTES)                   // 62976
#define VGS 72

__global__ __launch_bounds__(256, 3) void av_hmma_kernel()
{
    extern __shared__ f16 smh[];
    const int tid = threadIdx.x, lane = tid & 31, wid = tid >> 5;
    const int wr = wid >> 1, wc = wid & 1;
    const int n0 = blockIdx.x * 128;
    const int bh = blockIdx.y;
    const int b = bh / HEADS, h = bh % HEADS;
    const uint32_t smem_base = smem_to_u32(smh);

    const f16* ep = g_e    + ((size_t)bh * SEQ + n0) * SEQ;
    const f16* rp = g_rinv + ((size_t)(b * SEQ + n0)) * SEQ;
    const f16* vp = g_v16  + (size_t)bh * SEQ * HDIM;

    float acc[2][4][4] = {};

    const int lr0 = tid >> 2, lr1 = (tid + 256) >> 2;
    const int lc = tid & 3;
    const int vrow_ld = tid >> 3, vch_ld = tid & 7;

    auto issue = [&](int it, int s) {
        const int k0 = it * 32;
        const uint32_t sb = smem_base + (uint32_t)(s * AV_STG_BYTES);
        CP_ASYNC16(sb + swz(lr0, lc), ep + (size_t)lr0 * SEQ + k0 + lc * 8);
        CP_ASYNC16(sb + swz(lr1, lc), ep + (size_t)lr1 * SEQ + k0 + lc * 8);
        CP_ASYNC16(sb + AVE_BYTES + swz(lr0, lc), rp + (size_t)lr0 * SEQ + k0 + lc * 8);
        CP_ASYNC16(sb + AVE_BYTES + swz(lr1, lc), rp + (size_t)lr1 * SEQ + k0 + lc * 8);
        CP_ASYNC16(sb + AVE_BYTES + AVR_BYTES + (uint32_t)(vrow_ld * VGS + vch_ld * 8) * 2,
                   vp + (size_t)(k0 + vrow_ld) * HDIM + vch_ld * 8);
        CP_COMMIT();
    };

    const int NIT = SEQ / 32;
    issue(0, 0);
    issue(1, 1);

    for (int it = 0; it < NIT; ++it) {
        if (it + 1 < NIT) { CP_WAIT1(); } else { CP_WAIT0(); }
        __syncthreads();
        if (it + 2 < NIT) issue(it + 2, (it + 2) % 3);

        const uint32_t sb = smem_base + (uint32_t)((it % 3) * AV_STG_BYTES);
        const uint32_t rvb = sb + AVE_BYTES;
        const uint32_t vb = rvb + AVR_BYTES;

        #pragma unroll
        for (int ks = 0; ks < 2; ks++) {
            const uint32_t c0 = ks * 2 + (lane >> 4);
            uint32_t a[2][4];
            #pragma unroll
            for (int mt = 0; mt < 2; mt++) {
                uint32_t r = wr * 32 + mt * 16 + (lane & 15);
                uint32_t rv[4];
                ldmatrix_x4(a[mt][0], a[mt][1], a[mt][2], a[mt][3],
                            sb + swz(r, c0));
                ldmatrix_x4(rv[0], rv[1], rv[2], rv[3],
                            rvb + swz(r, c0));
                #pragma unroll
                for (int j = 0; j < 4; j++) a[mt][j] = hmul2u(a[mt][j], rv[j]);
            }
            const uint32_t kb = ks * 16;
            #pragma unroll
            for (int nb = 0; nb < 2; nb++) {
                const uint32_t d0 = wc * 32 + nb * 16;
                uint32_t vrow = kb + (lane & 7) + ((lane >> 3) & 1) * 8;
                uint32_t vcol = d0 + (lane >> 4) * 8;
                uint32_t b0, b1, b2, b3;
                ldmatrix_x4_trans(b0, b1, b2, b3, vb + (vrow * VGS + vcol) * 2);
                const int nt0 = nb * 2, nt1 = nb * 2 + 1;
                #pragma unroll
                for (int mt = 0; mt < 2; mt++) {
                    mma_f16(acc[mt][nt0], a[mt], b0, b1);
                    mma_f16(acc[mt][nt1], a[mt], b2, b3);
                }
            }
        }
    }

    // epilogue: O -> single fp16 at [b, n, h*64+d]
    #pragma unroll
    for (int mt = 0; mt < 2; mt++) {
        const int r = n0 + wr * 32 + mt * 16 + (lane >> 2);
        #pragma unroll
        for (int nt = 0; nt < 4; nt++) {
            const int c = wc * 32 + nt * 8 + 2 * (lane & 3);
            size_t i0 = ((size_t)(b * SEQ + r)) * INNER + h * HDIM + c;
            size_t i1 = ((size_t)(b * SEQ + r + 8)) * INNER + h * HDIM + c;
            *(__half2*)&g_o16[i0] = __floats2half2_rn(acc[mt][nt][0], acc[mt][nt][1]);
            *(__half2*)&g_o16[i1] = __floats2half2_rn(acc[mt][nt][2], acc[mt][nt][3]);
        }
    }
}

// =========================================================================
extern "C" void kernel_launch(void* const* d_in, const int* in_sizes, int n_in,
                              void* d_out, int out_size)
{
    const float* x     = (const float*)d_in[0];
    const float* w_qkv = (const float*)d_in[1];
    const float* w_out = (const float*)d_in[2];
    const float* b_out = (const float*)d_in[3];
    float* out = (float*)d_out;

    cudaFuncSetAttribute(hmma_f16_gemm_kernel<true>,
                         cudaFuncAttributeMaxDynamicSharedMemorySize,
                         HM_STAGES * 3 * MAT_BYTES);
    cudaFuncSetAttribute(hmma_f16_gemm_kernel<false>,
                         cudaFuncAttributeMaxDynamicSharedMemorySize,
                         HM_STAGES * 2 * MAT_BYTES);
    cudaFuncSetAttribute(score_hmma_kernel,
                         cudaFuncAttributeMaxDynamicSharedMemorySize, S3_SMEM_BYTES);
    cudaFuncSetAttribute(av_hmma_kernel,
                         cudaFuncAttributeMaxDynamicSharedMemorySize, AV_SMEM_BYTES);

    f16 *xh, *xl, *wq, *wo, *o16;
    cudaGetSymbolAddress((void**)&xh, g_xh16);
    cudaGetSymbolAddress((void**)&xl, g_xl16);
    cudaGetSymbolAddress((void**)&wq, g_wq16);
    cudaGetSymbolAddress((void**)&wo, g_wo16);
    cudaGetSymbolAddress((void**)&o16, g_o16);

    // Prep
    {
        int n4 = BATCH * SEQ * DIM / 4;
        split_f16_kernel<<<(n4 + 255) / 256, 256>>>(x, xh, xl, n4);
    }
    {
        dim3 grid(TRIPLE / 32, DIM / 32);
        transpose_f16_kernel<<<grid, dim3(32, 8)>>>(w_qkv, wq, DIM, TRIPLE);
    }
    {
        dim3 grid(DIM / 32, INNER / 32);
        transpose_f16_kernel<<<grid, dim3(32, 8)>>>(w_out, wo, INNER, DIM);
    }

    // K1: QKV projection (fp16 2-MMA, 4-stage)
    {
        dim3 grid(TRIPLE / 128, (BATCH * SEQ) / 128);
        hmma_f16_gemm_kernel<true><<<grid, 256, HM_STAGES * 3 * MAT_BYTES>>>(
            xh, xl, wq, nullptr, nullptr, 0);
    }
    // K2: scores + exp + head-sum -> E, rinv (fused)
    {
        dim3 grid(SEQ / 64, SEQ / 128, BATCH);
        score_hmma_kernel<<<grid, 256, S3_SMEM_BYTES>>>();
    }
    // K3: O = (E*rinv) @ V (fp16 HMMA, V single)
    {
        dim3 grid(SEQ / 128, BATCH * HEADS);
        av_hmma_kernel<<<grid, 256, AV_SMEM_BYTES>>>();
    }
    // K4: output projection (fp16 single-A, 4-stage) + bias
    {
        dim3 grid(DIM / 128, (BATCH * SEQ) / 128);
        hmma_f16_gemm_kernel<false><<<grid, 256, HM_STAGES * 2 * MAT_BYTES>>>(
            o16, nullptr, wo, b_out, out, 1);
    }
}

// round 15
// speedup vs baseline: 1.3736x; 1.1772x over previous
#include <cuda_runtime.h>
#include <cuda_bf16.h>
#include <cuda_fp16.h>
#include <cstdint>

// Problem constants
#define BATCH   8
#define SEQ     1024
#define DIM     768
#define HEADS   12
#define HDIM    64
#define INNER   768
#define TRIPLE  2304
#define SCALE   0.125f

typedef __half f16;

// ---------------- static scratch ----------------
__device__ __align__(128) f16 g_e[(size_t)BATCH * HEADS * SEQ * SEQ];   // E = exp(S)/16
__device__ __align__(128) f16 g_rinv[(size_t)BATCH * SEQ * SEQ];        // 1/sum_h E

__device__ __align__(128) f16 g_x16[BATCH * SEQ * DIM];     // x (single fp16)
__device__ __align__(128) f16 g_wq16[TRIPLE * DIM];         // transposed, hi only
__device__ __align__(128) f16 g_wo16[DIM * INNER];          // transposed, hi only
__device__ __align__(128) f16 g_o16[BATCH * SEQ * INNER];   // attention out (fp16)

__device__ __align__(128) f16 g_qh16[BATCH * HEADS * SEQ * HDIM];
__device__ __align__(128) f16 g_ql16[BATCH * HEADS * SEQ * HDIM];
__device__ __align__(128) f16 g_kh16[BATCH * HEADS * SEQ * HDIM];
__device__ __align__(128) f16 g_v16[BATCH * HEADS * SEQ * HDIM];    // V (fp16)

// ================= helpers =================
__device__ __forceinline__ uint32_t smem_to_u32(const void* p) {
    uint32_t a;
    asm("{ .reg .u64 t; cvta.to.shared.u64 t, %1; cvt.u32.u64 %0, t; }"
        : "=r"(a) : "l"(p));
    return a;
}
// swizzled byte offset within a [rows x 32 elems(16b)] tile (64B per row)
__device__ __forceinline__ uint32_t swz(uint32_t r, uint32_t c) {
    return (r * 4 + (c ^ ((r >> 1) & 3))) * 16;
}
__device__ __forceinline__ void ldmatrix_x4(uint32_t& r0, uint32_t& r1,
                                            uint32_t& r2, uint32_t& r3,
                                            uint32_t addr) {
    asm volatile("ldmatrix.sync.aligned.m8n8.x4.shared.b16 {%0,%1,%2,%3}, [%4];"
                 : "=r"(r0), "=r"(r1), "=r"(r2), "=r"(r3) : "r"(addr));
}
__device__ __forceinline__ void ldmatrix_x4_trans(uint32_t& r0, uint32_t& r1,
                                                  uint32_t& r2, uint32_t& r3,
                                                  uint32_t addr) {
    asm volatile("ldmatrix.sync.aligned.m8n8.x4.trans.shared.b16 {%0,%1,%2,%3}, [%4];"
                 : "=r"(r0), "=r"(r1), "=r"(r2), "=r"(r3) : "r"(addr));
}
__device__ __forceinline__ void mma_f16(float* c, const uint32_t* a,
                                        uint32_t b0, uint32_t b1) {
    asm volatile("mma.sync.aligned.m16n8k16.row.col.f32.f16.f16.f32 "
                 "{%0,%1,%2,%3}, {%4,%5,%6,%7}, {%8,%9}, {%0,%1,%2,%3};"
                 : "+f"(c[0]), "+f"(c[1]), "+f"(c[2]), "+f"(c[3])
                 : "r"(a[0]), "r"(a[1]), "r"(a[2]), "r"(a[3]),
                   "r"(b0), "r"(b1));
}
__device__ __forceinline__ uint32_t hmul2u(uint32_t a, uint32_t b) {
    __half2 r = __hmul2(*(__half2*)&a, *(__half2*)&b);
    return *(uint32_t*)&r;
}
#define CP_ASYNC16(sa, g) \
    asm volatile("cp.async.cg.shared.global [%0], [%1], 16;" :: "r"(sa), "l"(g))
#define CP_COMMIT() asm volatile("cp.async.commit_group;" ::: "memory")
#define CP_WAIT2()  asm volatile("cp.async.wait_group 2;" ::: "memory")
#define CP_WAIT1()  asm volatile("cp.async.wait_group 1;" ::: "memory")
#define CP_WAIT0()  asm volatile("cp.async.wait_group 0;" ::: "memory")

__device__ __forceinline__ float fast_exp_s(float x) {
    const float LOG2E = 1.4426950408889634f;
    const float MAGIC = 12582912.0f;
    float z = fmaf(x, LOG2E, MAGIC);
    int   e = __float_as_int(z) - 0x4B400000;
    float i = z - MAGIC;
    float f = fmaf(x, LOG2E, -i);
    float p = 1.5403531e-4f;
    p = fmaf(p, f, 1.3333558e-3f);
    p = fmaf(p, f, 9.6181291e-3f);
    p = fmaf(p, f, 5.5504109e-2f);
    p = fmaf(p, f, 2.4022651e-1f);
    p = fmaf(p, f, 6.9314718e-1f);
    p = fmaf(p, f, 1.0f);
    return __int_as_float(__float_as_int(p) + ((e - 4) << 23));
}
__device__ __forceinline__ void split2h(float2 v, __half2& h, __half2& l) {
    f16 hx = __float2half_rn(v.x), hy = __float2half_rn(v.y);
    h = __half2(hx, hy);
    l = __half2(__float2half_rn(v.x - __half2float(hx)),
                __float2half_rn(v.y - __half2float(hy)));
}

// =========================================================================
// Prep kernels
// =========================================================================
__global__ __launch_bounds__(256) void cvt_f16_kernel(
    const float* __restrict__ in, f16* __restrict__ outp, int n4)
{
    int i = blockIdx.x * 256 + threadIdx.x;
    if (i >= n4) return;
    float4 v = ((const float4*)in)[i];
    __half2* O = (__half2*)outp;
    O[2 * i]     = __floats2half2_rn(v.x, v.y);
    O[2 * i + 1] = __floats2half2_rn(v.z, v.w);
}

__global__ __launch_bounds__(256) void transpose_f16_kernel(
    const float* __restrict__ in, f16* __restrict__ outp, int R, int C)
{
    __shared__ float t[32][33];
    const int tx = threadIdx.x, ty = threadIdx.y;
    const int bx = blockIdx.x, by = blockIdx.y;
    #pragma unroll
    for (int i = 0; i < 4; i++) {
        int r = by * 32 + ty + i * 8;
        t[ty + i * 8][tx] = in[(size_t)r * C + bx * 32 + tx];
    }
    __syncthreads();
    #pragma unroll
    for (int i = 0; i < 4; i++) {
        int c = bx * 32 + ty + i * 8;
        int r = by * 32 + tx;
        outp[(size_t)c * R + r] = __float2half_rn(t[tx][ty + i * 8]);
    }
}

// =========================================================================
// fp16 GEMM (single-A, 1 MMA pass): C = A @ Bw^T. 128x128x32, 4-stage.
// mode 0: qkv epilogue; mode 1: oproj + bias -> fp32 out.
// =========================================================================
#define MAT_BYTES  8192
#define HM_STAGES  4
#define HM_STG     (2 * MAT_BYTES)
#define HM_SMEM_BYTES (HM_STAGES * HM_STG)   // 65536

__global__ __launch_bounds__(256, 2) void hmma_f16_gemm_kernel(
    const f16* __restrict__ Aa, const f16* __restrict__ Bw,
    const float* __restrict__ bias, float* __restrict__ outp, int mode)
{
    extern __shared__ f16 sm[];
    const int tid = threadIdx.x, lane = tid & 31, wid = tid >> 5;
    const int wr = wid >> 1, wc = wid & 1;
    const int bn = blockIdx.x * 128, bm = blockIdx.y * 128;
    const uint32_t smem_base = smem_to_u32(sm);

    float acc[2][8][4] = {};

    const int lr0 = tid >> 2, lr1 = (tid + 256) >> 2;
    const int lc = tid & 3;

    auto issue = [&](int it, int s) {
        const int k0 = it * 32;
        const uint32_t sb = smem_base + (uint32_t)(s * HM_STG);
        CP_ASYNC16(sb + swz(lr0, lc), Aa + (size_t)(bm + lr0) * DIM + k0 + lc * 8);
        CP_ASYNC16(sb + swz(lr1, lc), Aa + (size_t)(bm + lr1) * DIM + k0 + lc * 8);
        CP_ASYNC16(sb + MAT_BYTES + swz(lr0, lc),
                   Bw + (size_t)(bn + lr0) * DIM + k0 + lc * 8);
        CP_ASYNC16(sb + MAT_BYTES + swz(lr1, lc),
                   Bw + (size_t)(bn + lr1) * DIM + k0 + lc * 8);
        CP_COMMIT();
    };

    const int NIT = DIM / 32;   // 24
    issue(0, 0);
    issue(1, 1);
    issue(2, 2);

    for (int it = 0; it < NIT; ++it) {
        if (it + 2 < NIT)      { CP_WAIT2(); }
        else if (it + 1 < NIT) { CP_WAIT1(); }
        else                   { CP_WAIT0(); }
        __syncthreads();
        if (it + 3 < NIT) issue(it + 3, (it + 3) % HM_STAGES);

        const uint32_t sb = smem_base + (uint32_t)((it % HM_STAGES) * HM_STG);
        #pragma unroll
        for (int ks = 0; ks < 2; ks++) {
            const uint32_t c0 = ks * 2 + (lane >> 4);
            uint32_t ah[2][4], bf[4][4];
            #pragma unroll
            for (int mt = 0; mt < 2; mt++) {
                uint32_t r = wr * 32 + mt * 16 + (lane & 15);
                ldmatrix_x4(ah[mt][0], ah[mt][1], ah[mt][2], ah[mt][3],
                            sb + swz(r, c0));
            }
            #pragma unroll
            for (int p = 0; p < 4; p++) {
                uint32_t r = wc * 64 + p * 16 + (lane & 15);
                ldmatrix_x4(bf[p][0], bf[p][1], bf[p][2], bf[p][3],
                            sb + MAT_BYTES + swz(r, c0));
            }
            #pragma unroll
            for (int p = 0; p < 4; p++)
                #pragma unroll
                for (int mt = 0; mt < 2; mt++) {
                    mma_f16(acc[mt][2 * p + 0], ah[mt], bf[p][0], bf[p][2]);
                    mma_f16(acc[mt][2 * p + 1], ah[mt], bf[p][1], bf[p][3]);
                }
        }
    }

    // ---- epilogue ----
    #pragma unroll
    for (int mt = 0; mt < 2; mt++) {
        const int r = bm + wr * 32 + mt * 16 + (lane >> 2);
        #pragma unroll
        for (int nt = 0; nt < 8; nt++) {
            const int c = bn + wc * 64 + nt * 8 + 2 * (lane & 3);
            float2 v0 = make_float2(acc[mt][nt][0], acc[mt][nt][1]);
            float2 v1 = make_float2(acc[mt][nt][2], acc[mt][nt][3]);
            if (mode == 0) {
                int chunk = c / INNER;
                int e = c % INNER;
                int h = e >> 6, d = e & 63;
                int b0 = r >> 10, n0 = r & 1023;
                int r2 = r + 8;
                int b1 = r2 >> 10, n1 = r2 & 1023;
                size_t i0 = (((size_t)(b0 * HEADS + h) * SEQ) + n0) * HDIM + d;
                size_t i1 = (((size_t)(b1 * HEADS + h) * SEQ) + n1) * HDIM + d;
                if (chunk == 2) {
                    *(__half2*)&g_v16[i0] = __floats2half2_rn(v0.x, v0.y);
                    *(__half2*)&g_v16[i1] = __floats2half2_rn(v1.x, v1.y);
                } else if (chunk == 0) {
                    v0.x *= SCALE; v0.y *= SCALE;
                    v1.x *= SCALE; v1.y *= SCALE;
                    __half2 hh, ll;
                    split2h(v0, hh, ll);
                    *(__half2*)&g_qh16[i0] = hh;
                    *(__half2*)&g_ql16[i0] = ll;
                    split2h(v1, hh, ll);
                    *(__half2*)&g_qh16[i1] = hh;
                    *(__half2*)&g_ql16[i1] = ll;
                } else {
                    *(__half2*)&g_kh16[i0] = __floats2half2_rn(v0.x, v0.y);
                    *(__half2*)&g_kh16[i1] = __floats2half2_rn(v1.x, v1.y);
                }
            } else {
                float2 bq = *(const float2*)&bias[c];
                v0.x += bq.x; v0.y += bq.y;
                v1.x += bq.x; v1.y += bq.y;
                *(float2*)&outp[(size_t)r * DIM + c] = v0;
                *(float2*)&outp[(size_t)(r + 8) * DIM + c] = v1;
            }
        }
    }
}

// =========================================================================
// Score (fused): one CTA per (b, n0, m0), all 12 heads; writes E and rinv.
// Q fp16 hi/lo (2-MMA), K fp16 hi.
// =========================================================================
#define SGS 72
#define S3_Q_BYTES (128 * SGS * 2)                 // 18432
#define S3_K_BYTES (64 * SGS * 2)                  // 9216
#define S3_STG (2 * S3_Q_BYTES + S3_K_BYTES)       // 46080
#define S3_SMEM_BYTES (2 * S3_STG)                 // 92160

__global__ __launch_bounds__(256, 2) void score_hmma_kernel()
{
    extern __shared__ f16 smh[];
    const int tid = threadIdx.x, lane = tid & 31, wid = tid >> 5;
    const int wr = wid >> 1, wc = wid & 1;
    const int m0 = blockIdx.x * 64;
    const int n0 = blockIdx.y * 128;
    const int b  = blockIdx.z;
    const uint32_t smem_base = smem_to_u32(smh);

    auto issue = [&](int h, int s) {
        const size_t bh = (size_t)(b * HEADS + h);
        const f16* qh = g_qh16 + (bh * SEQ + n0) * HDIM;
        const f16* ql = g_ql16 + (bh * SEQ + n0) * HDIM;
        const f16* kh = g_kh16 + (bh * SEQ + m0) * HDIM;
        const uint32_t sb = smem_base + (uint32_t)(s * S3_STG);
        #pragma unroll
        for (int t = 0; t < 4; t++) {
            int i = tid + t * 256;
            int row = i >> 3, ch = i & 7;
            uint32_t doff = (uint32_t)(row * SGS + ch * 8) * 2;
            CP_ASYNC16(sb + doff, qh + (size_t)row * HDIM + ch * 8);
            CP_ASYNC16(sb + S3_Q_BYTES + doff, ql + (size_t)row * HDIM + ch * 8);
        }
        #pragma unroll
        for (int t = 0; t < 2; t++) {
            int i = tid + t * 256;
            int row = i >> 3, ch = i & 7;
            CP_ASYNC16(sb + 2 * S3_Q_BYTES + (uint32_t)(row * SGS + ch * 8) * 2,
                       kh + (size_t)row * HDIM + ch * 8);
        }
        CP_COMMIT();
    };

    issue(0, 0);
    issue(1, 1);

    float sumf[2][4][4] = {};

    for (int h = 0; h < HEADS; ++h) {
        if (h + 1 < HEADS) { CP_WAIT1(); } else { CP_WAIT0(); }
        __syncthreads();

        const uint32_t sb = smem_base + (uint32_t)((h & 1) * S3_STG);
        const uint32_t kbse = sb + 2 * S3_Q_BYTES;

        float acc[2][4][4] = {};
        #pragma unroll
        for (int ks = 0; ks < 4; ks++) {
            const uint32_t col = ks * 16 + (lane >> 4) * 8;
            uint32_t ah[2][4], al[2][4], bf[2][4];
            #pragma unroll
            for (int mt = 0; mt < 2; mt++) {
                uint32_t r = wr * 32 + mt * 16 + (lane & 15);
                ldmatrix_x4(ah[mt][0], ah[mt][1], ah[mt][2], ah[mt][3],
                            sb + (r * SGS + col) * 2);
                ldmatrix_x4(al[mt][0], al[mt][1], al[mt][2], al[mt][3],
                            sb + S3_Q_BYTES + (r * SGS + col) * 2);
            }
            #pragma unroll
            for (int p = 0; p < 2; p++) {
                uint32_t r = wc * 32 + p * 16 + (lane & 15);
                ldmatrix_x4(bf[p][0], bf[p][1], bf[p][2], bf[p][3],
                            kbse + (r * SGS + col) * 2);
            }
            #pragma unroll
            for (int p = 0; p < 2; p++)
                #pragma unroll
                for (int mt = 0; mt < 2; mt++) {
                    mma_f16(acc[mt][2 * p + 0], ah[mt], bf[p][0], bf[p][2]);
                    mma_f16(acc[mt][2 * p + 1], ah[mt], bf[p][1], bf[p][3]);
                }
            #pragma unroll
            for (int p = 0; p < 2; p++)
                #pragma unroll
                for (int mt = 0; mt < 2; mt++) {
                    mma_f16(acc[mt][2 * p + 0], al[mt], bf[p][0], bf[p][2]);
                    mma_f16(acc[mt][2 * p + 1], al[mt], bf[p][1], bf[p][3]);
                }
        }

        // epilogue: E for this head + accumulate head-sum (fp32)
        f16* ebase = g_e + ((size_t)(b * HEADS + h) * SEQ) * SEQ;
        #pragma unroll
        for (int mt = 0; mt < 2; mt++) {
            const int r = n0 + wr * 32 + mt * 16 + (lane >> 2);
            #pragma unroll
            for (int nt = 0; nt < 4; nt++) {
                const int c = m0 + wc * 32 + nt * 8 + 2 * (lane & 3);
                float e0 = fast_exp_s(acc[mt][nt][0]);
                float e1 = fast_exp_s(acc[mt][nt][1]);
                float e2 = fast_exp_s(acc[mt][nt][2]);
                float e3 = fast_exp_s(acc[mt][nt][3]);
                sumf[mt][nt][0] += e0; sumf[mt][nt][1] += e1;
                sumf[mt][nt][2] += e2; sumf[mt][nt][3] += e3;
                *(__half2*)&ebase[(size_t)r * SEQ + c] = __floats2half2_rn(e0, e1);
                *(__half2*)&ebase[(size_t)(r + 8) * SEQ + c] = __floats2half2_rn(e2, e3);
            }
        }

        __syncthreads();
        if (h + 2 < HEADS) issue(h + 2, h & 1);
    }

    // rinv epilogue
    #pragma unroll
    for (int mt = 0; mt < 2; mt++) {
        const int r = n0 + wr * 32 + mt * 16 + (lane >> 2);
        #pragma unroll
        for (int nt = 0; nt < 4; nt++) {
            const int c = m0 + wc * 32 + nt * 8 + 2 * (lane & 3);
            *(__half2*)&g_rinv[((size_t)(b * SEQ + r)) * SEQ + c] =
                __floats2half2_rn(1.0f / sumf[mt][nt][0], 1.0f / sumf[mt][nt][1]);
            *(__half2*)&g_rinv[((size_t)(b * SEQ + r + 8)) * SEQ + c] =
                __floats2half2_rn(1.0f / sumf[mt][nt][2], 1.0f / sumf[mt][nt][3]);
        }
    }
}

// =========================================================================
// AV HMMA (fp16): O = (E*rinv) @ V, V single fp16 (1 MMA pass).
// =========================================================================
#define AVE_BYTES 8192
#define AVR_BYTES 8192
#define AVV_BYTES 4608
#define AV_STG_BYTES (AVE_BYTES + AVR_BYTES + AVV_BYTES)   // 20992
#define AV_SMEM_BYTES (3 * AV_STG_BYTES)                   // 62976
#define VGS 72

__global__ __launch_bounds__(256, 3) void av_hmma_kernel()
{
    extern __shared__ f16 smh[];
    const int tid = threadIdx.x, lane = tid & 31, wid = tid >> 5;
    const int wr = wid >> 1, wc = wid & 1;
    const int n0 = blockIdx.x * 128;
    const int bh = blockIdx.y;
    const int b = bh / HEADS, h = bh % HEADS;
    const uint32_t smem_base = smem_to_u32(smh);

    const f16* ep = g_e    + ((size_t)bh * SEQ + n0) * SEQ;
    const f16* rp = g_rinv + ((size_t)(b * SEQ + n0)) * SEQ;
    const f16* vp = g_v16  + (size_t)bh * SEQ * HDIM;

    float acc[2][4][4] = {};

    const int lr0 = tid >> 2, lr1 = (tid + 256) >> 2;
    const int lc = tid & 3;
    const int vrow_ld = tid >> 3, vch_ld = tid & 7;

    auto issue = [&](int it, int s) {
        const int k0 = it * 32;
        const uint32_t sb = smem_base + (uint32_t)(s * AV_STG_BYTES);
        CP_ASYNC16(sb + swz(lr0, lc), ep + (size_t)lr0 * SEQ + k0 + lc * 8);
        CP_ASYNC16(sb + swz(lr1, lc), ep + (size_t)lr1 * SEQ + k0 + lc * 8);
        CP_ASYNC16(sb + AVE_BYTES + swz(lr0, lc), rp + (size_t)lr0 * SEQ + k0 + lc * 8);
        CP_ASYNC16(sb + AVE_BYTES + swz(lr1, lc), rp + (size_t)lr1 * SEQ + k0 + lc * 8);
        CP_ASYNC16(sb + AVE_BYTES + AVR_BYTES + (uint32_t)(vrow_ld * VGS + vch_ld * 8) * 2,
                   vp + (size_t)(k0 + vrow_ld) * HDIM + vch_ld * 8);
        CP_COMMIT();
    };

    const int NIT = SEQ / 32;
    issue(0, 0);
    issue(1, 1);

    for (int it = 0; it < NIT; ++it) {
        if (it + 1 < NIT) { CP_WAIT1(); } else { CP_WAIT0(); }
        __syncthreads();
        if (it + 2 < NIT) issue(it + 2, (it + 2) % 3);

        const uint32_t sb = smem_base + (uint32_t)((it % 3) * AV_STG_BYTES);
        const uint32_t rvb = sb + AVE_BYTES;
        const uint32_t vb = rvb + AVR_BYTES;

        #pragma unroll
        for (int ks = 0; ks < 2; ks++) {
            const uint32_t c0 = ks * 2 + (lane >> 4);
            uint32_t a[2][4];
            #pragma unroll
            for (int mt = 0; mt < 2; mt++) {
                uint32_t r = wr * 32 + mt * 16 + (lane & 15);
                uint32_t rv[4];
                ldmatrix_x4(a[mt][0], a[mt][1], a[mt][2], a[mt][3],
                            sb + swz(r, c0));
                ldmatrix_x4(rv[0], rv[1], rv[2], rv[3],
                            rvb + swz(r, c0));
                #pragma unroll
                for (int j = 0; j < 4; j++) a[mt][j] = hmul2u(a[mt][j], rv[j]);
            }
            const uint32_t kb = ks * 16;
            #pragma unroll
            for (int nb = 0; nb < 2; nb++) {
                const uint32_t d0 = wc * 32 + nb * 16;
                uint32_t vrow = kb + (lane & 7) + ((lane >> 3) & 1) * 8;
                uint32_t vcol = d0 + (lane >> 4) * 8;
                uint32_t b0, b1, b2, b3;
                ldmatrix_x4_trans(b0, b1, b2, b3, vb + (vrow * VGS + vcol) * 2);
                const int nt0 = nb * 2, nt1 = nb * 2 + 1;
                #pragma unroll
                for (int mt = 0; mt < 2; mt++) {
                    mma_f16(acc[mt][nt0], a[mt], b0, b1);
                    mma_f16(acc[mt][nt1], a[mt], b2, b3);
                }
            }
        }
    }

    // epilogue: O -> single fp16 at [b, n, h*64+d]
    #pragma unroll
    for (int mt = 0; mt < 2; mt++) {
        const int r = n0 + wr * 32 + mt * 16 + (lane >> 2);
        #pragma unroll
        for (int nt = 0; nt < 4; nt++) {
            const int c = wc * 32 + nt * 8 + 2 * (lane & 3);
            size_t i0 = ((size_t)(b * SEQ + r)) * INNER + h * HDIM + c;
            size_t i1 = ((size_t)(b * SEQ + r + 8)) * INNER + h * HDIM + c;
            *(__half2*)&g_o16[i0] = __floats2half2_rn(acc[mt][nt][0], acc[mt][nt][1]);
            *(__half2*)&g_o16[i1] = __floats2half2_rn(acc[mt][nt][2], acc[mt][nt][3]);
        }
    }
}

// =========================================================================
extern "C" void kernel_launch(void* const* d_in, const int* in_sizes, int n_in,
                              void* d_out, int out_size)
{
    const float* x     = (const float*)d_in[0];
    const float* w_qkv = (const float*)d_in[1];
    const float* w_out = (const float*)d_in[2];
    const float* b_out = (const float*)d_in[3];
    float* out = (float*)d_out;

    cudaFuncSetAttribute(hmma_f16_gemm_kernel,
                         cudaFuncAttributeMaxDynamicSharedMemorySize, HM_SMEM_BYTES);
    cudaFuncSetAttribute(score_hmma_kernel,
                         cudaFuncAttributeMaxDynamicSharedMemorySize, S3_SMEM_BYTES);
    cudaFuncSetAttribute(av_hmma_kernel,
                         cudaFuncAttributeMaxDynamicSharedMemorySize, AV_SMEM_BYTES);

    f16 *x16, *wq, *wo, *o16;
    cudaGetSymbolAddress((void**)&x16, g_x16);
    cudaGetSymbolAddress((void**)&wq,  g_wq16);
    cudaGetSymbolAddress((void**)&wo,  g_wo16);
    cudaGetSymbolAddress((void**)&o16, g_o16);

    // Prep
    {
        int n4 = BATCH * SEQ * DIM / 4;
        cvt_f16_kernel<<<(n4 + 255) / 256, 256>>>(x, x16, n4);
    }
    {
        dim3 grid(TRIPLE / 32, DIM / 32);
        transpose_f16_kernel<<<grid, dim3(32, 8)>>>(w_qkv, wq, DIM, TRIPLE);
    }
    {
        dim3 grid(DIM / 32, INNER / 32);
        transpose_f16_kernel<<<grid, dim3(32, 8)>>>(w_out, wo, INNER, DIM);
    }

    // K1: QKV projection (fp16 single-A, 4-stage)
    {
        dim3 grid(TRIPLE / 128, (BATCH * SEQ) / 128);
        hmma_f16_gemm_kernel<<<grid, 256, HM_SMEM_BYTES>>>(x16, wq, nullptr, nullptr, 0);
    }
    // K2: scores + exp + head-sum -> E, rinv (fused)
    {
        dim3 grid(SEQ / 64, SEQ / 128, BATCH);
        score_hmma_kernel<<<grid, 256, S3_SMEM_BYTES>>>();
    }
    // K3: O = (E*rinv) @ V (fp16 HMMA, V single)
    {
        dim3 grid(SEQ / 128, BATCH * HEADS);
        av_hmma_kernel<<<grid, 256, AV_SMEM_BYTES>>>();
    }
    // K4: output projection (fp16 single-A, 4-stage) + bias
    {
        dim3 grid(DIM / 128, (BATCH * SEQ) / 128);
        hmma_f16_gemm_kernel<<<grid, 256, HM_SMEM_BYTES>>>(o16, wo, b_out, out, 1);
    }
}

// round 16
// speedup vs baseline: 1.5106x; 1.0997x over previous
#include <cuda_runtime.h>
#include <cuda_bf16.h>
#include <cuda_fp16.h>
#include <cstdint>

// Problem constants
#define BATCH   8
#define SEQ     1024
#define DIM     768
#define HEADS   12
#define HDIM    64
#define INNER   768
#define TRIPLE  2304
#define SCALE   0.125f

typedef __half f16;

// ---------------- static scratch ----------------
__device__ __align__(128) f16 g_e[(size_t)BATCH * HEADS * SEQ * SEQ];   // E = exp(S)/16
__device__ __align__(128) f16 g_rinv[(size_t)BATCH * SEQ * SEQ];        // 1/sum_h E

__device__ __align__(128) f16 g_x16[BATCH * SEQ * DIM];     // x (fp16)
__device__ __align__(128) f16 g_wq16[TRIPLE * DIM];         // transposed
__device__ __align__(128) f16 g_wo16[DIM * INNER];          // transposed
__device__ __align__(128) f16 g_o16[BATCH * SEQ * INNER];   // attention out (fp16)

__device__ __align__(128) f16 g_q16[BATCH * HEADS * SEQ * HDIM];    // Q (fp16, pre-scaled)
__device__ __align__(128) f16 g_k16[BATCH * HEADS * SEQ * HDIM];    // K (fp16)
__device__ __align__(128) f16 g_v16[BATCH * HEADS * SEQ * HDIM];    // V (fp16)

// ================= helpers =================
__device__ __forceinline__ uint32_t smem_to_u32(const void* p) {
    uint32_t a;
    asm("{ .reg .u64 t; cvta.to.shared.u64 t, %1; cvt.u32.u64 %0, t; }"
        : "=r"(a) : "l"(p));
    return a;
}
// swizzled byte offset within a [rows x 32 elems(16b)] tile (64B per row)
__device__ __forceinline__ uint32_t swz(uint32_t r, uint32_t c) {
    return (r * 4 + (c ^ ((r >> 1) & 3))) * 16;
}
__device__ __forceinline__ void ldmatrix_x4(uint32_t& r0, uint32_t& r1,
                                            uint32_t& r2, uint32_t& r3,
                                            uint32_t addr) {
    asm volatile("ldmatrix.sync.aligned.m8n8.x4.shared.b16 {%0,%1,%2,%3}, [%4];"
                 : "=r"(r0), "=r"(r1), "=r"(r2), "=r"(r3) : "r"(addr));
}
__device__ __forceinline__ void ldmatrix_x4_trans(uint32_t& r0, uint32_t& r1,
                                                  uint32_t& r2, uint32_t& r3,
                                                  uint32_t addr) {
    asm volatile("ldmatrix.sync.aligned.m8n8.x4.trans.shared.b16 {%0,%1,%2,%3}, [%4];"
                 : "=r"(r0), "=r"(r1), "=r"(r2), "=r"(r3) : "r"(addr));
}
__device__ __forceinline__ void mma_f16(float* c, const uint32_t* a,
                                        uint32_t b0, uint32_t b1) {
    asm volatile("mma.sync.aligned.m16n8k16.row.col.f32.f16.f16.f32 "
                 "{%0,%1,%2,%3}, {%4,%5,%6,%7}, {%8,%9}, {%0,%1,%2,%3};"
                 : "+f"(c[0]), "+f"(c[1]), "+f"(c[2]), "+f"(c[3])
                 : "r"(a[0]), "r"(a[1]), "r"(a[2]), "r"(a[3]),
                   "r"(b0), "r"(b1));
}
__device__ __forceinline__ uint32_t hmul2u(uint32_t a, uint32_t b) {
    __half2 r = __hmul2(*(__half2*)&a, *(__half2*)&b);
    return *(uint32_t*)&r;
}
#define CP_ASYNC16(sa, g) \
    asm volatile("cp.async.cg.shared.global [%0], [%1], 16;" :: "r"(sa), "l"(g))
#define CP_COMMIT() asm volatile("cp.async.commit_group;" ::: "memory")
#define CP_WAIT2()  asm volatile("cp.async.wait_group 2;" ::: "memory")
#define CP_WAIT1()  asm volatile("cp.async.wait_group 1;" ::: "memory")
#define CP_WAIT0()  asm volatile("cp.async.wait_group 0;" ::: "memory")

__device__ __forceinline__ float fast_exp_s(float x) {
    const float LOG2E = 1.4426950408889634f;
    const float MAGIC = 12582912.0f;
    float z = fmaf(x, LOG2E, MAGIC);
    int   e = __float_as_int(z) - 0x4B400000;
    float i = z - MAGIC;
    float f = fmaf(x, LOG2E, -i);
    float p = 1.5403531e-4f;
    p = fmaf(p, f, 1.3333558e-3f);
    p = fmaf(p, f, 9.6181291e-3f);
    p = fmaf(p, f, 5.5504109e-2f);
    p = fmaf(p, f, 2.4022651e-1f);
    p = fmaf(p, f, 6.9314718e-1f);
    p = fmaf(p, f, 1.0f);
    return __int_as_float(__float_as_int(p) + ((e - 4) << 23));
}

// =========================================================================
// Prep kernels
// =========================================================================
__global__ __launch_bounds__(256) void cvt_f16_kernel(
    const float* __restrict__ in, f16* __restrict__ outp, int n4)
{
    int i = blockIdx.x * 256 + threadIdx.x;
    if (i >= n4) return;
    float4 v = ((const float4*)in)[i];
    __half2* O = (__half2*)outp;
    O[2 * i]     = __floats2half2_rn(v.x, v.y);
    O[2 * i + 1] = __floats2half2_rn(v.z, v.w);
}

__global__ __launch_bounds__(256) void transpose_f16_kernel(
    const float* __restrict__ in, f16* __restrict__ outp, int R, int C)
{
    __shared__ float t[32][33];
    const int tx = threadIdx.x, ty = threadIdx.y;
    const int bx = blockIdx.x, by = blockIdx.y;
    #pragma unroll
    for (int i = 0; i < 4; i++) {
        int r = by * 32 + ty + i * 8;
        t[ty + i * 8][tx] = in[(size_t)r * C + bx * 32 + tx];
    }
    __syncthreads();
    #pragma unroll
    for (int i = 0; i < 4; i++) {
        int c = bx * 32 + ty + i * 8;
        int r = by * 32 + tx;
        outp[(size_t)c * R + r] = __float2half_rn(t[tx][ty + i * 8]);
    }
}

// =========================================================================
// fp16 GEMM (single-A): C = A @ Bw^T. 128x128x32, 4-stage, 1 barrier/iter.
// mode 0: qkv epilogue (Q scaled fp16, K fp16, V fp16); mode 1: oproj+bias.
// =========================================================================
#define MAT_BYTES  8192
#define HM_STAGES  4
#define HM_STG     (2 * MAT_BYTES)
#define HM_SMEM_BYTES (HM_STAGES * HM_STG)   // 65536

__global__ __launch_bounds__(256, 2) void hmma_f16_gemm_kernel(
    const f16* __restrict__ Aa, const f16* __restrict__ Bw,
    const float* __restrict__ bias, float* __restrict__ outp, int mode)
{
    extern __shared__ f16 sm[];
    const int tid = threadIdx.x, lane = tid & 31, wid = tid >> 5;
    const int wr = wid >> 1, wc = wid & 1;
    const int bn = blockIdx.x * 128, bm = blockIdx.y * 128;
    const uint32_t smem_base = smem_to_u32(sm);

    float acc[2][8][4] = {};

    const int lr0 = tid >> 2, lr1 = (tid + 256) >> 2;
    const int lc = tid & 3;

    auto issue = [&](int it, int s) {
        const int k0 = it * 32;
        const uint32_t sb = smem_base + (uint32_t)(s * HM_STG);
        CP_ASYNC16(sb + swz(lr0, lc), Aa + (size_t)(bm + lr0) * DIM + k0 + lc * 8);
        CP_ASYNC16(sb + swz(lr1, lc), Aa + (size_t)(bm + lr1) * DIM + k0 + lc * 8);
        CP_ASYNC16(sb + MAT_BYTES + swz(lr0, lc),
                   Bw + (size_t)(bn + lr0) * DIM + k0 + lc * 8);
        CP_ASYNC16(sb + MAT_BYTES + swz(lr1, lc),
                   Bw + (size_t)(bn + lr1) * DIM + k0 + lc * 8);
        CP_COMMIT();
    };

    const int NIT = DIM / 32;   // 24
    issue(0, 0);
    issue(1, 1);
    issue(2, 2);

    for (int it = 0; it < NIT; ++it) {
        if (it + 2 < NIT)      { CP_WAIT2(); }
        else if (it + 1 < NIT) { CP_WAIT1(); }
        else                   { CP_WAIT0(); }
        __syncthreads();
        if (it + 3 < NIT) issue(it + 3, (it + 3) % HM_STAGES);

        const uint32_t sb = smem_base + (uint32_t)((it % HM_STAGES) * HM_STG);
        #pragma unroll
        for (int ks = 0; ks < 2; ks++) {
            const uint32_t c0 = ks * 2 + (lane >> 4);
            uint32_t ah[2][4], bf[4][4];
            #pragma unroll
            for (int mt = 0; mt < 2; mt++) {
                uint32_t r = wr * 32 + mt * 16 + (lane & 15);
                ldmatrix_x4(ah[mt][0], ah[mt][1], ah[mt][2], ah[mt][3],
                            sb + swz(r, c0));
            }
            #pragma unroll
            for (int p = 0; p < 4; p++) {
                uint32_t r = wc * 64 + p * 16 + (lane & 15);
                ldmatrix_x4(bf[p][0], bf[p][1], bf[p][2], bf[p][3],
                            sb + MAT_BYTES + swz(r, c0));
            }
            #pragma unroll
            for (int p = 0; p < 4; p++)
                #pragma unroll
                for (int mt = 0; mt < 2; mt++) {
                    mma_f16(acc[mt][2 * p + 0], ah[mt], bf[p][0], bf[p][2]);
                    mma_f16(acc[mt][2 * p + 1], ah[mt], bf[p][1], bf[p][3]);
                }
        }
    }

    // ---- epilogue ----
    #pragma unroll
    for (int mt = 0; mt < 2; mt++) {
        const int r = bm + wr * 32 + mt * 16 + (lane >> 2);
        #pragma unroll
        for (int nt = 0; nt < 8; nt++) {
            const int c = bn + wc * 64 + nt * 8 + 2 * (lane & 3);
            float2 v0 = make_float2(acc[mt][nt][0], acc[mt][nt][1]);
            float2 v1 = make_float2(acc[mt][nt][2], acc[mt][nt][3]);
            if (mode == 0) {
                int chunk = c / INNER;
                int e = c % INNER;
                int h = e >> 6, d = e & 63;
                int b0 = r >> 10, n0 = r & 1023;
                int r2 = r + 8;
                int b1 = r2 >> 10, n1 = r2 & 1023;
                size_t i0 = (((size_t)(b0 * HEADS + h) * SEQ) + n0) * HDIM + d;
                size_t i1 = (((size_t)(b1 * HEADS + h) * SEQ) + n1) * HDIM + d;
                f16* dst;
                if (chunk == 2)      dst = g_v16;
                else if (chunk == 1) dst = g_k16;
                else {
                    dst = g_q16;
                    v0.x *= SCALE; v0.y *= SCALE;
                    v1.x *= SCALE; v1.y *= SCALE;
                }
                *(__half2*)&dst[i0] = __floats2half2_rn(v0.x, v0.y);
                *(__half2*)&dst[i1] = __floats2half2_rn(v1.x, v1.y);
            } else {
                float2 bq = *(const float2*)&bias[c];
                v0.x += bq.x; v0.y += bq.y;
                v1.x += bq.x; v1.y += bq.y;
                *(float2*)&outp[(size_t)r * DIM + c] = v0;
                *(float2*)&outp[(size_t)(r + 8) * DIM + c] = v1;
            }
        }
    }
}

// =========================================================================
// Score (fused): one CTA per (b, n0, m0), all 12 heads; writes E and rinv.
// Q fp16 (1 MMA pass), K fp16.
// =========================================================================
#define SGS 72
#define S3_Q_BYTES (128 * SGS * 2)                 // 18432
#define S3_K_BYTES (64 * SGS * 2)                  // 9216
#define S3_STG (S3_Q_BYTES + S3_K_BYTES)           // 27648
#define S3_SMEM_BYTES (2 * S3_STG)                 // 55296

__global__ __launch_bounds__(256, 2) void score_hmma_kernel()
{
    extern __shared__ f16 smh[];
    const int tid = threadIdx.x, lane = tid & 31, wid = tid >> 5;
    const int wr = wid >> 1, wc = wid & 1;
    const int m0 = blockIdx.x * 64;
    const int n0 = blockIdx.y * 128;
    const int b  = blockIdx.z;
    const uint32_t smem_base = smem_to_u32(smh);

    auto issue = [&](int h, int s) {
        const size_t bh = (size_t)(b * HEADS + h);
        const f16* q = g_q16 + (bh * SEQ + n0) * HDIM;
        const f16* k = g_k16 + (bh * SEQ + m0) * HDIM;
        const uint32_t sb = smem_base + (uint32_t)(s * S3_STG);
        #pragma unroll
        for (int t = 0; t < 4; t++) {
            int i = tid + t * 256;
            int row = i >> 3, ch = i & 7;
            CP_ASYNC16(sb + (uint32_t)(row * SGS + ch * 8) * 2,
                       q + (size_t)row * HDIM + ch * 8);
        }
        #pragma unroll
        for (int t = 0; t < 2; t++) {
            int i = tid + t * 256;
            int row = i >> 3, ch = i & 7;
            CP_ASYNC16(sb + S3_Q_BYTES + (uint32_t)(row * SGS + ch * 8) * 2,
                       k + (size_t)row * HDIM + ch * 8);
        }
        CP_COMMIT();
    };

    issue(0, 0);
    issue(1, 1);

    float sumf[2][4][4] = {};

    for (int h = 0; h < HEADS; ++h) {
        if (h + 1 < HEADS) { CP_WAIT1(); } else { CP_WAIT0(); }
        __syncthreads();

        const uint32_t sb = smem_base + (uint32_t)((h & 1) * S3_STG);
        const uint32_t kbse = sb + S3_Q_BYTES;

        float acc[2][4][4] = {};
        #pragma unroll
        for (int ks = 0; ks < 4; ks++) {
            const uint32_t col = ks * 16 + (lane >> 4) * 8;
            uint32_t aq[2][4], bf[2][4];
            #pragma unroll
            for (int mt = 0; mt < 2; mt++) {
                uint32_t r = wr * 32 + mt * 16 + (lane & 15);
                ldmatrix_x4(aq[mt][0], aq[mt][1], aq[mt][2], aq[mt][3],
                            sb + (r * SGS + col) * 2);
            }
            #pragma unroll
            for (int p = 0; p < 2; p++) {
                uint32_t r = wc * 32 + p * 16 + (lane & 15);
                ldmatrix_x4(bf[p][0], bf[p][1], bf[p][2], bf[p][3],
                            kbse + (r * SGS + col) * 2);
            }
            #pragma unroll
            for (int p = 0; p < 2; p++)
                #pragma unroll
                for (int mt = 0; mt < 2; mt++) {
                    mma_f16(acc[mt][2 * p + 0], aq[mt], bf[p][0], bf[p][2]);
                    mma_f16(acc[mt][2 * p + 1], aq[mt], bf[p][1], bf[p][3]);
                }
        }

        // epilogue: E for this head + accumulate head-sum (fp32)
        f16* ebase = g_e + ((size_t)(b * HEADS + h) * SEQ) * SEQ;
        #pragma unroll
        for (int mt = 0; mt < 2; mt++) {
            const int r = n0 + wr * 32 + mt * 16 + (lane >> 2);
            #pragma unroll
            for (int nt = 0; nt < 4; nt++) {
                const int c = m0 + wc * 32 + nt * 8 + 2 * (lane & 3);
                float e0 = fast_exp_s(acc[mt][nt][0]);
                float e1 = fast_exp_s(acc[mt][nt][1]);
                float e2 = fast_exp_s(acc[mt][nt][2]);
                float e3 = fast_exp_s(acc[mt][nt][3]);
                sumf[mt][nt][0] += e0; sumf[mt][nt][1] += e1;
                sumf[mt][nt][2] += e2; sumf[mt][nt][3] += e3;
                *(__half2*)&ebase[(size_t)r * SEQ + c] = __floats2half2_rn(e0, e1);
                *(__half2*)&ebase[(size_t)(r + 8) * SEQ + c] = __floats2half2_rn(e2, e3);
            }
        }

        __syncthreads();
        if (h + 2 < HEADS) issue(h + 2, h & 1);
    }

    // rinv epilogue
    #pragma unroll
    for (int mt = 0; mt < 2; mt++) {
        const int r = n0 + wr * 32 + mt * 16 + (lane >> 2);
        #pragma unroll
        for (int nt = 0; nt < 4; nt++) {
            const int c = m0 + wc * 32 + nt * 8 + 2 * (lane & 3);
            *(__half2*)&g_rinv[((size_t)(b * SEQ + r)) * SEQ + c] =
                __floats2half2_rn(1.0f / sumf[mt][nt][0], 1.0f / sumf[mt][nt][1]);
            *(__half2*)&g_rinv[((size_t)(b * SEQ + r + 8)) * SEQ + c] =
                __floats2half2_rn(1.0f / sumf[mt][nt][2], 1.0f / sumf[mt][nt][3]);
        }
    }
}

// =========================================================================
// AV HMMA (fp16): O = (E*rinv) @ V, V single fp16 (1 MMA pass).
// =========================================================================
#define AVE_BYTES 8192
#define AVR_BYTES 8192
#define AVV_BYTES 4608
#define AV_STG_BYTES (AVE_BYTES + AVR_BYTES + AVV_BYTES)   // 20992
#define AV_SMEM_BYTES (3 * AV_STG_BYTES)                   // 62976
#define VGS 72

__global__ __launch_bounds__(256, 3) void av_hmma_kernel()
{
    extern __shared__ f16 smh[];
    const int tid = threadIdx.x, lane = tid & 31, wid = tid >> 5;
    const int wr = wid >> 1, wc = wid & 1;
    const int n0 = blockIdx.x * 128;
    const int bh = blockIdx.y;
    const int b = bh / HEADS, h = bh % HEADS;
    const uint32_t smem_base = smem_to_u32(smh);

    const f16* ep = g_e    + ((size_t)bh * SEQ + n0) * SEQ;
    const f16* rp = g_rinv + ((size_t)(b * SEQ + n0)) * SEQ;
    const f16* vp = g_v16  + (size_t)bh * SEQ * HDIM;

    float acc[2][4][4] = {};

    const int lr0 = tid >> 2, lr1 = (tid + 256) >> 2;
    const int lc = tid & 3;
    const int vrow_ld = tid >> 3, vch_ld = tid & 7;

    auto issue = [&](int it, int s) {
        const int k0 = it * 32;
        const uint32_t sb = smem_base + (uint32_t)(s * AV_STG_BYTES);
        CP_ASYNC16(sb + swz(lr0, lc), ep + (size_t)lr0 * SEQ + k0 + lc * 8);
        CP_ASYNC16(sb + swz(lr1, lc), ep + (size_t)lr1 * SEQ + k0 + lc * 8);
        CP_ASYNC16(sb + AVE_BYTES + swz(lr0, lc), rp + (size_t)lr0 * SEQ + k0 + lc * 8);
        CP_ASYNC16(sb + AVE_BYTES + swz(lr1, lc), rp + (size_t)lr1 * SEQ + k0 + lc * 8);
        CP_ASYNC16(sb + AVE_BYTES + AVR_BYTES + (uint32_t)(vrow_ld * VGS + vch_ld * 8) * 2,
                   vp + (size_t)(k0 + vrow_ld) * HDIM + vch_ld * 8);
        CP_COMMIT();
    };

    const int NIT = SEQ / 32;
    issue(0, 0);
    issue(1, 1);

    for (int it = 0; it < NIT; ++it) {
        if (it + 1 < NIT) { CP_WAIT1(); } else { CP_WAIT0(); }
        __syncthreads();
        if (it + 2 < NIT) issue(it + 2, (it + 2) % 3);

        const uint32_t sb = smem_base + (uint32_t)((it % 3) * AV_STG_BYTES);
        const uint32_t rvb = sb + AVE_BYTES;
        const uint32_t vb = rvb + AVR_BYTES;

        #pragma unroll
        for (int ks = 0; ks < 2; ks++) {
            const uint32_t c0 = ks * 2 + (lane >> 4);
            uint32_t a[2][4];
            #pragma unroll
            for (int mt = 0; mt < 2; mt++) {
                uint32_t r = wr * 32 + mt * 16 + (lane & 15);
                uint32_t rv[4];
                ldmatrix_x4(a[mt][0], a[mt][1], a[mt][2], a[mt][3],
                            sb + swz(r, c0));
                ldmatrix_x4(rv[0], rv[1], rv[2], rv[3],
                            rvb + swz(r, c0));
                #pragma unroll
                for (int j = 0; j < 4; j++) a[mt][j] = hmul2u(a[mt][j], rv[j]);
            }
            const uint32_t kb = ks * 16;
            #pragma unroll
            for (int nb = 0; nb < 2; nb++) {
                const uint32_t d0 = wc * 32 + nb * 16;
                uint32_t vrow = kb + (lane & 7) + ((lane >> 3) & 1) * 8;
                uint32_t vcol = d0 + (lane >> 4) * 8;
                uint32_t b0, b1, b2, b3;
                ldmatrix_x4_trans(b0, b1, b2, b3, vb + (vrow * VGS + vcol) * 2);
                const int nt0 = nb * 2, nt1 = nb * 2 + 1;
                #pragma unroll
                for (int mt = 0; mt < 2; mt++) {
                    mma_f16(acc[mt][nt0], a[mt], b0, b1);
                    mma_f16(acc[mt][nt1], a[mt], b2, b3);
                }
            }
        }
    }

    // epilogue: O -> single fp16 at [b, n, h*64+d]
    #pragma unroll
    for (int mt = 0; mt < 2; mt++) {
        const int r = n0 + wr * 32 + mt * 16 + (lane >> 2);
        #pragma unroll
        for (int nt = 0; nt < 4; nt++) {
            const int c = wc * 32 + nt * 8 + 2 * (lane & 3);
            size_t i0 = ((size_t)(b * SEQ + r)) * INNER + h * HDIM + c;
            size_t i1 = ((size_t)(b * SEQ + r + 8)) * INNER + h * HDIM + c;
            *(__half2*)&g_o16[i0] = __floats2half2_rn(acc[mt][nt][0], acc[mt][nt][1]);
            *(__half2*)&g_o16[i1] = __floats2half2_rn(acc[mt][nt][2], acc[mt][nt][3]);
        }
    }
}

// =========================================================================
extern "C" void kernel_launch(void* const* d_in, const int* in_sizes, int n_in,
                              void* d_out, int out_size)
{
    const float* x     = (const float*)d_in[0];
    const float* w_qkv = (const float*)d_in[1];
    const float* w_out = (const float*)d_in[2];
    const float* b_out = (const float*)d_in[3];
    float* out = (float*)d_out;

    cudaFuncSetAttribute(hmma_f16_gemm_kernel,
                         cudaFuncAttributeMaxDynamicSharedMemorySize, HM_SMEM_BYTES);
    cudaFuncSetAttribute(score_hmma_kernel,
                         cudaFuncAttributeMaxDynamicSharedMemorySize, S3_SMEM_BYTES);
    cudaFuncSetAttribute(av_hmma_kernel,
                         cudaFuncAttributeMaxDynamicSharedMemorySize, AV_SMEM_BYTES);

    f16 *x16, *wq, *wo, *o16;
    cudaGetSymbolAddress((void**)&x16, g_x16);
    cudaGetSymbolAddress((void**)&wq,  g_wq16);
    cudaGetSymbolAddress((void**)&wo,  g_wo16);
    cudaGetSymbolAddress((void**)&o16, g_o16);

    // Prep
    {
        int n4 = BATCH * SEQ * DIM / 4;
        cvt_f16_kernel<<<(n4 + 255) / 256, 256>>>(x, x16, n4);
    }
    {
        dim3 grid(TRIPLE / 32, DIM / 32);
        transpose_f16_kernel<<<grid, dim3(32, 8)>>>(w_qkv, wq, DIM, TRIPLE);
    }
    {
        dim3 grid(DIM / 32, INNER / 32);
        transpose_f16_kernel<<<grid, dim3(32, 8)>>>(w_out, wo, INNER, DIM);
    }

    // K1: QKV projection (fp16 single-A, 4-stage)
    {
        dim3 grid(TRIPLE / 128, (BATCH * SEQ) / 128);
        hmma_f16_gemm_kernel<<<grid, 256, HM_SMEM_BYTES>>>(x16, wq, nullptr, nullptr, 0);
    }
    // K2: scores + exp + head-sum -> E, rinv (fused, 1-MMA)
    {
        dim3 grid(SEQ / 64, SEQ / 128, BATCH);
        score_hmma_kernel<<<grid, 256, S3_SMEM_BYTES>>>();
    }
    // K3: O = (E*rinv) @ V (fp16 HMMA, V single)
    {
        dim3 grid(SEQ / 128, BATCH * HEADS);
        av_hmma_kernel<<<grid, 256, AV_SMEM_BYTES>>>();
    }
    // K4: output projection (fp16 single-A, 4-stage) + bias
    {
        dim3 grid(DIM / 128, (BATCH * SEQ) / 128);
        hmma_f16_gemm_kernel<<<grid, 256, HM_SMEM_BYTES>>>(o16, wo, b_out, out, 1);
    }
}